// round 9
// baseline (speedup 1.0000x reference)
#include <cuda_runtime.h>
#include <math.h>
#include <stdint.h>

// ---------------------------------------------------------------------------
// Problem constants
// ---------------------------------------------------------------------------
constexpr int H    = 2048;
constexpr int NH   = 16;
constexpr int NOPE = 128;
constexpr int ROPE = 64;
constexpr int VD   = 128;
constexpr int QR   = 1024;
constexpr int KVR  = 512;
constexpr int BB   = 2;       // batch
constexpr int S    = 2048;    // seq len
constexpr int T    = BB * S;  // 4096 tokens
constexpr float EPS = 1e-6f;
constexpr float SM_SCALE = 0.07216878364870323f; // 1/sqrt(192)

// ---------------------------------------------------------------------------
// Device scratch (allocation-free rule: __device__ globals)
// ---------------------------------------------------------------------------
__device__ float g_cq   [T * QR];
__device__ float g_qnope[T * NH * NOPE];
__device__ float g_qrope[T * NH * ROPE];
__device__ float g_ckv  [T * KVR];
__device__ float g_knope[T * NH * NOPE];
__device__ float g_v    [T * NH * VD];
__device__ float g_krope[T * ROPE];
__device__ float g_attn [T * NH * VD];
__device__ float g_ctab [S * (ROPE / 2)];
__device__ float g_stab [S * (ROPE / 2)];

// ---------------------------------------------------------------------------
// tf32 helpers
// ---------------------------------------------------------------------------
__device__ __forceinline__ float to_tf32(float x) {
    uint32_t u;
    asm("cvt.rna.tf32.f32 %0, %1;" : "=r"(u) : "f"(x));
    return __uint_as_float(u);
}
__device__ __forceinline__ float4 to_tf32x4(float4 v) {
    return make_float4(to_tf32(v.x), to_tf32(v.y), to_tf32(v.z), to_tf32(v.w));
}

__device__ __forceinline__ void mma_tf32(float& c0, float& c1, float& c2, float& c3,
                                         float a0, float a1, float a2, float a3,
                                         float b0, float b1)
{
    uint32_t ua0 = __float_as_uint(a0), ua1 = __float_as_uint(a1);
    uint32_t ua2 = __float_as_uint(a2), ua3 = __float_as_uint(a3);
    uint32_t ub0 = __float_as_uint(b0), ub1 = __float_as_uint(b1);
    asm volatile(
        "mma.sync.aligned.m16n8k8.row.col.f32.tf32.tf32.f32 "
        "{%0,%1,%2,%3}, {%4,%5,%6,%7}, {%8,%9}, {%0,%1,%2,%3};\n"
        : "+f"(c0), "+f"(c1), "+f"(c2), "+f"(c3)
        : "r"(ua0), "r"(ua1), "r"(ua2), "r"(ua3), "r"(ub0), "r"(ub1));
}

// Fragment-order smem stores (values already tf32-rounded by producers).
template<int KSTEPS>
__device__ __forceinline__ void st_afrag_raw(float* F, int m, int k, float4 v) {
    float* dst = F + (((m >> 4) * KSTEPS + (k >> 3)) * 32 + (m & 7) * 4 + (k & 3)) * 4
                   + ((m >> 3) & 1) + (((k >> 2) & 1) << 1);
    dst[0]  = v.x;
    dst[4]  = v.y;
    dst[8]  = v.z;
    dst[12] = v.w;
}
template<int KSTEPS>
__device__ __forceinline__ void st_bfrag_raw(float* F, int r, int d, float4 v) {
    float* dst = F + (((r >> 3) * KSTEPS + (d >> 3)) * 32 + (r & 7) * 4 + (d & 3)) * 2
                   + ((d >> 2) & 1);
    dst[0] = v.x;
    dst[2] = v.y;
    dst[4] = v.z;
    dst[6] = v.w;
}

// ---------------------------------------------------------------------------
// tf32 tensor-core GEMM (proven): C[M,N] = A[M,K] @ B[K,N].
// round_out != 0 -> store tf32-rounded results (for attention inputs).
// ---------------------------------------------------------------------------
constexpr int AS_STRIDE = 20;
constexpr int BS_STRIDE = 136;

__global__ void __launch_bounds__(256)
tf32_gemm_kernel(const float* __restrict__ A, const float* __restrict__ B,
                 float* __restrict__ C, int M, int N, int K, int round_out)
{
    __shared__ float As[2][128][AS_STRIDE];
    __shared__ float Bs[2][16][BS_STRIDE];

    const int tid  = threadIdx.x;
    const int lane = tid & 31;
    const int warp = tid >> 5;
    const int qid  = lane >> 2;
    const int rid  = lane & 3;
    const int wr   = (warp >> 2) * 64;
    const int wc   = (warp & 3) * 32;

    const int rowBase = blockIdx.y * 128;
    const int colBase = blockIdx.x * 128;

    const int ar0 = tid >> 2;
    const int ar1 = ar0 + 64;
    const int ac  = (tid & 3) * 4;
    const int bk0 = tid >> 5;
    const int bk1 = bk0 + 8;
    const int bn  = (tid & 31) * 4;
    const int gn  = colBase + bn;
    const bool bok = (gn < N);

    float acc[4][4][4];
#pragma unroll
    for (int i = 0; i < 4; i++)
#pragma unroll
        for (int j = 0; j < 4; j++)
#pragma unroll
            for (int c = 0; c < 4; c++) acc[i][j][c] = 0.f;

    const int nt = K / 16;
    float4 ra0, ra1, rb0, rb1;

    ra0 = *(const float4*)&A[(size_t)(rowBase + ar0) * K + ac];
    ra1 = *(const float4*)&A[(size_t)(rowBase + ar1) * K + ac];
    rb0 = bok ? *(const float4*)&B[(size_t)bk0 * N + gn] : make_float4(0,0,0,0);
    rb1 = bok ? *(const float4*)&B[(size_t)bk1 * N + gn] : make_float4(0,0,0,0);
    *(float4*)&As[0][ar0][ac] = to_tf32x4(ra0);
    *(float4*)&As[0][ar1][ac] = to_tf32x4(ra1);
    *(float4*)&Bs[0][bk0][bn] = to_tf32x4(rb0);
    *(float4*)&Bs[0][bk1][bn] = to_tf32x4(rb1);
    __syncthreads();

    for (int t = 0; t < nt; t++) {
        const int buf = t & 1;

        if (t + 1 < nt) {
            const int k0 = (t + 1) * 16;
            ra0 = *(const float4*)&A[(size_t)(rowBase + ar0) * K + k0 + ac];
            ra1 = *(const float4*)&A[(size_t)(rowBase + ar1) * K + k0 + ac];
            rb0 = bok ? *(const float4*)&B[(size_t)(k0 + bk0) * N + gn] : make_float4(0,0,0,0);
            rb1 = bok ? *(const float4*)&B[(size_t)(k0 + bk1) * N + gn] : make_float4(0,0,0,0);
        }

#pragma unroll
        for (int ks = 0; ks < 16; ks += 8) {
            float a[4][4], b[4][2];
#pragma unroll
            for (int i = 0; i < 4; i++) {
                const float* p0 = &As[buf][wr + i * 16 + qid][ks + rid];
                const float* p1 = &As[buf][wr + i * 16 + qid + 8][ks + rid];
                a[i][0] = p0[0];
                a[i][1] = p1[0];
                a[i][2] = p0[4];
                a[i][3] = p1[4];
            }
#pragma unroll
            for (int j = 0; j < 4; j++) {
                b[j][0] = Bs[buf][ks + rid][wc + j * 8 + qid];
                b[j][1] = Bs[buf][ks + rid + 4][wc + j * 8 + qid];
            }
#pragma unroll
            for (int i = 0; i < 4; i++)
#pragma unroll
                for (int j = 0; j < 4; j++)
                    mma_tf32(acc[i][j][0], acc[i][j][1], acc[i][j][2], acc[i][j][3],
                             a[i][0], a[i][1], a[i][2], a[i][3],
                             b[j][0], b[j][1]);
        }

        if (t + 1 < nt) {
            const int nb = (t + 1) & 1;
            *(float4*)&As[nb][ar0][ac] = to_tf32x4(ra0);
            *(float4*)&As[nb][ar1][ac] = to_tf32x4(ra1);
            *(float4*)&Bs[nb][bk0][bn] = to_tf32x4(rb0);
            *(float4*)&Bs[nb][bk1][bn] = to_tf32x4(rb1);
        }
        __syncthreads();
    }

#pragma unroll
    for (int i = 0; i < 4; i++) {
        const int r0 = rowBase + wr + i * 16 + qid;
#pragma unroll
        for (int j = 0; j < 4; j++) {
            const int col = colBase + wc + j * 8 + rid * 2;
            if (col < N) {
                float2 v0 = make_float2(acc[i][j][0], acc[i][j][1]);
                float2 v1 = make_float2(acc[i][j][2], acc[i][j][3]);
                if (round_out) {
                    v0.x = to_tf32(v0.x); v0.y = to_tf32(v0.y);
                    v1.x = to_tf32(v1.x); v1.y = to_tf32(v1.y);
                }
                *(float2*)&C[(size_t)r0 * N + col]       = v0;
                *(float2*)&C[(size_t)(r0 + 8) * N + col] = v1;
            }
        }
    }
}

// ---------------------------------------------------------------------------
// RMSNorm (in place)
// ---------------------------------------------------------------------------
__global__ void rmsnorm_kernel(float* __restrict__ x,
                               const float* __restrict__ scale, int D)
{
    __shared__ float red[32];
    float* p = x + (size_t)blockIdx.x * D;

    float ss = 0.f;
    for (int d = threadIdx.x; d < D; d += blockDim.x) {
        float v = p[d];
        ss += v * v;
    }
#pragma unroll
    for (int o = 16; o; o >>= 1) ss += __shfl_xor_sync(0xffffffffu, ss, o);
    if ((threadIdx.x & 31) == 0) red[threadIdx.x >> 5] = ss;
    __syncthreads();
    if (threadIdx.x < 32) {
        float v = (threadIdx.x < (blockDim.x >> 5)) ? red[threadIdx.x] : 0.f;
#pragma unroll
        for (int o = 16; o; o >>= 1) v += __shfl_xor_sync(0xffffffffu, v, o);
        if (threadIdx.x == 0) red[0] = v;
    }
    __syncthreads();
    float inv = rsqrtf(red[0] / (float)D + EPS);
    for (int d = threadIdx.x; d < D; d += blockDim.x)
        p[d] = p[d] * inv * scale[d];
}

// ---------------------------------------------------------------------------
// RoPE tables / application (rope outputs tf32-rounded: consumed only by mma)
// ---------------------------------------------------------------------------
__global__ void rope_table_kernel(float* __restrict__ ctab, float* __restrict__ stab)
{
    int idx = blockIdx.x * blockDim.x + threadIdx.x;
    if (idx >= S * (ROPE / 2)) return;
    int i = idx % (ROPE / 2);
    int s = idx / (ROPE / 2);
    float freq = (float)pow(10000.0, -((double)(2 * i)) / (double)ROPE);
    float ang  = (float)s * freq;
    double a   = (double)ang;
    ctab[idx] = (float)cos(a);
    stab[idx] = (float)sin(a);
}

__global__ void rope_q_kernel(float* __restrict__ q,
                              const float* __restrict__ ctab,
                              const float* __restrict__ stab)
{
    int idx = blockIdx.x * blockDim.x + threadIdx.x;
    if (idx >= T * NH * (ROPE / 2)) return;
    int i   = idx & 31;
    int rem = idx >> 5;
    int h   = rem & (NH - 1);
    int tok = rem >> 4;
    int s   = tok & (S - 1);
    float c  = ctab[s * 32 + i];
    float sn = stab[s * 32 + i];
    float* p = q + (size_t)tok * (NH * ROPE) + h * ROPE + 2 * i;
    float x1 = p[0], x2 = p[1];
    p[0] = to_tf32(x1 * c - x2 * sn);
    p[1] = to_tf32(x1 * sn + x2 * c);
}

__global__ void rope_k_kernel(float* __restrict__ k,
                              const float* __restrict__ ctab,
                              const float* __restrict__ stab)
{
    int idx = blockIdx.x * blockDim.x + threadIdx.x;
    if (idx >= T * (ROPE / 2)) return;
    int i   = idx & 31;
    int tok = idx >> 5;
    int s   = tok & (S - 1);
    float c  = ctab[s * 32 + i];
    float sn = stab[s * 32 + i];
    float* p = k + (size_t)tok * ROPE + 2 * i;
    float x1 = p[0], x2 = p[1];
    p[0] = to_tf32((x1 * c - x2 * sn) * 0.0625f);   // /NH folded in
    p[1] = to_tf32((x1 * sn + x2 * c) * 0.0625f);
}

// ---------------------------------------------------------------------------
// Flash attention: BQ=64, BKT=32, 256 threads, ~101KB smem -> 2 CTAs/SM.
// Cross-CTA overlap hides barrier/latency stalls. Register K/V prefetch,
// tf32 mma for QK and PV, strided conflict-free softmax mapping.
// ---------------------------------------------------------------------------
constexpr int BQ  = 64;
constexpr int BKT = 32;
constexpr int VSTR = 136;  // ≡8 mod 32: conflict-free B-operand reads
constexpr int PSTR = 36;   // ≡4 mod 32: conflict-free A-operand reads

struct AttnSmem {
    float Qf[4 * 24 * 32 * 4];   // A-frag: 4 mtiles x 24 ksteps    (49.2 KB)
    float Kf[4 * 24 * 32 * 2];   // B-frag: 4 ntiles x 24 ksteps    (24.6 KB)
    float V[BKT][VSTR];          // (17.4 KB)
    float P[BQ][PSTR];           // (9.2 KB)
    float alpha[BQ];
    float invl[BQ];
};

__global__ void __launch_bounds__(256, 2)
attn_kernel(const float* __restrict__ qn, const float* __restrict__ qr,
            const float* __restrict__ kn, const float* __restrict__ kr,
            const float* __restrict__ v,  float* __restrict__ out)
{
    extern __shared__ char smraw[];
    AttnSmem& sm = *reinterpret_cast<AttnSmem*>(smraw);

    const int qt = (gridDim.x - 1) - blockIdx.x;   // heavy blocks first
    const int h  = blockIdx.y;
    const int b  = blockIdx.z;
    const int tid = threadIdx.x;
    const int lane = tid & 31;
    const int warp = tid >> 5;          // 0..7
    const int qid  = lane >> 2;
    const int rid  = lane & 3;
    const int qb = b * S + qt * BQ;

    // QK warp mapping: rows (warp&3)*16, cols (warp>>2)*16 (2 n-tiles)
    const int mtile = warp & 3;
    const int ntb   = (warp >> 2) * 2;
    // PV warp mapping: rows (warp&3)*16 (+qid,+8), cols (warp>>2)*64
    const int row0 = mtile * 16 + qid;
    const int nbv  = (warp >> 2) * 64;

    // per-thread staging indices
    const int krn[4] = { tid >> 5, (tid + 256) >> 5, (tid + 512) >> 5, (tid + 768) >> 5 };
    const int kcn    = (tid & 31) * 4;
    const int krr[2] = { tid >> 4, (tid + 256) >> 4 };
    const int kcr    = (tid & 15) * 4;

    // ---- stage Q tile [64 x 192] into fragment layout ----
    for (int idx = tid; idx < BQ * 32; idx += 256) {
        int r = idx >> 5, dq = (idx & 31) * 4;
        st_afrag_raw<24>(sm.Qf, r, dq,
            *(const float4*)&qn[(size_t)(qb + r) * (NH * NOPE) + h * NOPE + dq]);
    }
    for (int idx = tid; idx < BQ * 16; idx += 256) {
        int r = idx >> 4, dq = (idx & 15) * 4;
        st_afrag_raw<24>(sm.Qf, r, 128 + dq,
            *(const float4*)&qr[(size_t)(qb + r) * (NH * ROPE) + h * ROPE + dq]);
    }

    // softmax mapping: 4 threads/row, strided cols (conflict-free)
    const int srow = tid >> 2, squad = tid & 3;

    float m = -1e30f, l = 0.f;
    float acc[8][4];
#pragma unroll
    for (int j = 0; j < 8; j++)
#pragma unroll
        for (int c = 0; c < 4; c++) acc[j][c] = 0.f;

    const int nkt = 2 * qt + 2;   // keys up to (qt+1)*64

    // ---- prefetch tile 0 into registers ----
    float4 kb[6], vb[4];
    {
        const int kbT = b * S;
#pragma unroll
        for (int i = 0; i < 4; i++)
            kb[i] = *(const float4*)&kn[(size_t)(kbT + krn[i]) * (NH * NOPE) + h * NOPE + kcn];
#pragma unroll
        for (int i = 0; i < 2; i++)
            kb[4 + i] = *(const float4*)&kr[(size_t)(kbT + krr[i]) * ROPE + kcr];
#pragma unroll
        for (int i = 0; i < 4; i++)
            vb[i] = *(const float4*)&v[(size_t)(kbT + krn[i]) * (NH * VD) + h * VD + kcn];
    }

    for (int kt = 0; kt < nkt; kt++) {
        __syncthreads();   // Kf/V free and Q staging visible

        // ---- store prefetched tile to smem ----
#pragma unroll
        for (int i = 0; i < 4; i++) st_bfrag_raw<24>(sm.Kf, krn[i], kcn, kb[i]);
#pragma unroll
        for (int i = 0; i < 2; i++) st_bfrag_raw<24>(sm.Kf, krr[i], 128 + kcr, kb[4 + i]);
#pragma unroll
        for (int i = 0; i < 4; i++) *(float4*)&sm.V[krn[i]][kcn] = vb[i];
        __syncthreads();   // tile kt ready

        // ---- issue prefetch for tile kt+1 ----
        if (kt + 1 < nkt) {
            const int kbT = b * S + (kt + 1) * BKT;
#pragma unroll
            for (int i = 0; i < 4; i++)
                kb[i] = *(const float4*)&kn[(size_t)(kbT + krn[i]) * (NH * NOPE) + h * NOPE + kcn];
#pragma unroll
            for (int i = 0; i < 2; i++)
                kb[4 + i] = *(const float4*)&kr[(size_t)(kbT + krr[i]) * ROPE + kcr];
#pragma unroll
            for (int i = 0; i < 4; i++)
                vb[i] = *(const float4*)&v[(size_t)(kbT + krn[i]) * (NH * VD) + h * VD + kcn];
        }

        // ---- scores via tf32 mma: each warp 16x16 of the 64x32 tile ----
        {
            float c[2][4];
#pragma unroll
            for (int j = 0; j < 2; j++)
#pragma unroll
                for (int cc = 0; cc < 4; cc++) c[j][cc] = 0.f;

#pragma unroll
            for (int ks = 0; ks < 24; ks++) {
                float4 a = *(const float4*)&sm.Qf[((mtile * 24 + ks) * 32 + lane) * 4];
#pragma unroll
                for (int j = 0; j < 2; j++) {
                    float2 bb = *(const float2*)&sm.Kf[(((ntb + j) * 24 + ks) * 32 + lane) * 2];
                    mma_tf32(c[j][0], c[j][1], c[j][2], c[j][3],
                             a.x, a.y, a.z, a.w, bb.x, bb.y);
                }
            }

            const bool diag = (kt >= 2 * qt);
#pragma unroll
            for (int j = 0; j < 2; j++) {
                int col = (ntb + j) * 8 + rid * 2;
                int ki0 = kt * BKT + col;
                float s0 = c[j][0] * SM_SCALE, s1 = c[j][1] * SM_SCALE;
                float s2 = c[j][2] * SM_SCALE, s3 = c[j][3] * SM_SCALE;
                if (diag) {
                    int qi0 = qt * BQ + row0;
                    int qi1 = qi0 + 8;
                    if (ki0     > qi0) s0 = -1e9f;
                    if (ki0 + 1 > qi0) s1 = -1e9f;
                    if (ki0     > qi1) s2 = -1e9f;
                    if (ki0 + 1 > qi1) s3 = -1e9f;
                }
                *(float2*)&sm.P[row0][col]     = make_float2(s0, s1);
                *(float2*)&sm.P[row0 + 8][col] = make_float2(s2, s3);
            }
        }
        __syncthreads();

        // ---- online softmax: 8 strided cols per thread (conflict-free) ----
        {
            float sv[8];
            float tmax = -1e30f;
#pragma unroll
            for (int jj = 0; jj < 8; jj++) {
                sv[jj] = sm.P[srow][jj * 4 + squad];
                tmax = fmaxf(tmax, sv[jj]);
            }
            tmax = fmaxf(tmax, __shfl_xor_sync(0xffffffffu, tmax, 1));
            tmax = fmaxf(tmax, __shfl_xor_sync(0xffffffffu, tmax, 2));
            float mnew = fmaxf(m, tmax);
            float al   = __expf(m - mnew);
            float ps = 0.f;
#pragma unroll
            for (int jj = 0; jj < 8; jj++) {
                float p = __expf(sv[jj] - mnew);
                sm.P[srow][jj * 4 + squad] = to_tf32(p);
                ps += p;
            }
            ps += __shfl_xor_sync(0xffffffffu, ps, 1);
            ps += __shfl_xor_sync(0xffffffffu, ps, 2);
            l = l * al + ps;
            m = mnew;
            if (squad == 0) sm.alpha[srow] = al;
        }
        __syncthreads();

        // ---- O = O*alpha + P @ V via tf32 mma ----
        {
            const float al0 = sm.alpha[row0];
            const float al1 = sm.alpha[row0 + 8];
#pragma unroll
            for (int j = 0; j < 8; j++) {
                acc[j][0] *= al0; acc[j][1] *= al0;
                acc[j][2] *= al1; acc[j][3] *= al1;
            }
#pragma unroll
            for (int ks = 0; ks < 4; ks++) {
                const float a0 = sm.P[row0]    [ks * 8 + rid];
                const float a1 = sm.P[row0 + 8][ks * 8 + rid];
                const float a2 = sm.P[row0]    [ks * 8 + rid + 4];
                const float a3 = sm.P[row0 + 8][ks * 8 + rid + 4];
#pragma unroll
                for (int j = 0; j < 8; j++) {
                    const float b0 = sm.V[ks * 8 + rid]    [nbv + j * 8 + qid];
                    const float b1 = sm.V[ks * 8 + rid + 4][nbv + j * 8 + qid];
                    mma_tf32(acc[j][0], acc[j][1], acc[j][2], acc[j][3],
                             a0, a1, a2, a3, b0, b1);
                }
            }
        }
    }

    if (squad == 0) sm.invl[srow] = 1.f / l;
    __syncthreads();

    // ---- epilogue ----
    {
        const float il0 = sm.invl[row0];
        const float il1 = sm.invl[row0 + 8];
        const int tok0 = qb + row0;
        const int tok1 = tok0 + 8;
#pragma unroll
        for (int j = 0; j < 8; j++) {
            const int col = nbv + j * 8 + rid * 2;
            *(float2*)&out[(size_t)tok0 * (NH * VD) + h * VD + col] =
                make_float2(acc[j][0] * il0, acc[j][1] * il0);
            *(float2*)&out[(size_t)tok1 * (NH * VD) + h * VD + col] =
                make_float2(acc[j][2] * il1, acc[j][3] * il1);
        }
    }
}

// ---------------------------------------------------------------------------
// Launch
// ---------------------------------------------------------------------------
static void launch_gemm(const float* A, const float* B, float* C,
                        int M, int N, int K, int round_out = 0)
{
    dim3 grid((N + 127) / 128, (M + 127) / 128);
    tf32_gemm_kernel<<<grid, 256>>>(A, B, C, M, N, K, round_out);
}

extern "C" void kernel_launch(void* const* d_in, const int* in_sizes, int n_in,
                              void* d_out, int out_size)
{
    const float* x         = (const float*)d_in[0];
    const float* W_cq      = (const float*)d_in[1];
    const float* q_scale   = (const float*)d_in[2];
    const float* W_dq_nope = (const float*)d_in[3];
    const float* W_dq_rope = (const float*)d_in[4];
    const float* W_ckv     = (const float*)d_in[5];
    const float* kv_scale  = (const float*)d_in[6];
    const float* W_dk_nope = (const float*)d_in[7];
    const float* W_dv      = (const float*)d_in[8];
    const float* W_krope   = (const float*)d_in[9];
    const float* W_o       = (const float*)d_in[10];
    float* out = (float*)d_out;

    float *cq, *qn, *qr, *ckv, *kn, *vv, *kr, *att, *ctab, *stab;
    cudaGetSymbolAddress((void**)&cq,  g_cq);
    cudaGetSymbolAddress((void**)&qn,  g_qnope);
    cudaGetSymbolAddress((void**)&qr,  g_qrope);
    cudaGetSymbolAddress((void**)&ckv, g_ckv);
    cudaGetSymbolAddress((void**)&kn,  g_knope);
    cudaGetSymbolAddress((void**)&vv,  g_v);
    cudaGetSymbolAddress((void**)&kr,  g_krope);
    cudaGetSymbolAddress((void**)&att, g_attn);
    cudaGetSymbolAddress((void**)&ctab, g_ctab);
    cudaGetSymbolAddress((void**)&stab, g_stab);

    // RoPE tables
    rope_table_kernel<<<(S * 32 + 255) / 256, 256>>>(ctab, stab);

    // Q path
    launch_gemm(x, W_cq, cq, T, QR, H);
    rmsnorm_kernel<<<T, 256>>>(cq, q_scale, QR);
    launch_gemm(cq, W_dq_nope, qn, T, NH * NOPE, QR, 1);   // tf32-rounded out
    launch_gemm(cq, W_dq_rope, qr, T, NH * ROPE, QR);
    rope_q_kernel<<<(T * NH * 32 + 255) / 256, 256>>>(qr, ctab, stab);

    // KV path
    launch_gemm(x, W_ckv, ckv, T, KVR, H);
    rmsnorm_kernel<<<T, 256>>>(ckv, kv_scale, KVR);
    launch_gemm(ckv, W_dk_nope, kn, T, NH * NOPE, KVR, 1); // tf32-rounded out
    launch_gemm(ckv, W_dv, vv, T, NH * VD, KVR, 1);        // tf32-rounded out
    launch_gemm(x, W_krope, kr, T, ROPE, H);
    rope_k_kernel<<<(T * 32 + 255) / 256, 256>>>(kr, ctab, stab);

    // Attention
    cudaFuncSetAttribute((const void*)attn_kernel,
                         cudaFuncAttributeMaxDynamicSharedMemorySize,
                         (int)sizeof(AttnSmem));
    attn_kernel<<<dim3(S / BQ, NH, BB), 256, sizeof(AttnSmem)>>>(qn, qr, kn, kr, vv, att);

    // Output projection
    launch_gemm(att, W_o, out, T, H, NH * VD);
}

// round 10
// speedup vs baseline: 1.1019x; 1.1019x over previous
#include <cuda_runtime.h>
#include <math.h>
#include <stdint.h>

// ---------------------------------------------------------------------------
// Problem constants
// ---------------------------------------------------------------------------
constexpr int H    = 2048;
constexpr int NH   = 16;
constexpr int NOPE = 128;
constexpr int ROPE = 64;
constexpr int VD   = 128;
constexpr int QR   = 1024;
constexpr int KVR  = 512;
constexpr int BB   = 2;       // batch
constexpr int S    = 2048;    // seq len
constexpr int T    = BB * S;  // 4096 tokens
constexpr float EPS = 1e-6f;
constexpr float SM_SCALE = 0.07216878364870323f;          // 1/sqrt(192)
constexpr float SM_SCALE2 = 0.10412105626079532f;         // SM_SCALE * log2(e)
constexpr float MASK2 = -1.4426950408889634e9f;           // -1e9 * log2(e)

// ---------------------------------------------------------------------------
// Device scratch (allocation-free rule: __device__ globals)
// ---------------------------------------------------------------------------
__device__ float g_cq   [T * QR];
__device__ float g_qnope[T * NH * NOPE];
__device__ float g_qrope[T * NH * ROPE];
__device__ float g_ckv  [T * KVR];
__device__ float g_knope[T * NH * NOPE];
__device__ float g_v    [T * NH * VD];
__device__ float g_krope[T * ROPE];
__device__ float g_attn [T * NH * VD];
__device__ float g_ctab [S * (ROPE / 2)];
__device__ float g_stab [S * (ROPE / 2)];

// ---------------------------------------------------------------------------
// tf32 helpers
// ---------------------------------------------------------------------------
__device__ __forceinline__ float to_tf32(float x) {
    uint32_t u;
    asm("cvt.rna.tf32.f32 %0, %1;" : "=r"(u) : "f"(x));
    return __uint_as_float(u);
}
__device__ __forceinline__ float4 to_tf32x4(float4 v) {
    return make_float4(to_tf32(v.x), to_tf32(v.y), to_tf32(v.z), to_tf32(v.w));
}

__device__ __forceinline__ void mma_tf32(float& c0, float& c1, float& c2, float& c3,
                                         float a0, float a1, float a2, float a3,
                                         float b0, float b1)
{
    uint32_t ua0 = __float_as_uint(a0), ua1 = __float_as_uint(a1);
    uint32_t ua2 = __float_as_uint(a2), ua3 = __float_as_uint(a3);
    uint32_t ub0 = __float_as_uint(b0), ub1 = __float_as_uint(b1);
    asm volatile(
        "mma.sync.aligned.m16n8k8.row.col.f32.tf32.tf32.f32 "
        "{%0,%1,%2,%3}, {%4,%5,%6,%7}, {%8,%9}, {%0,%1,%2,%3};\n"
        : "+f"(c0), "+f"(c1), "+f"(c2), "+f"(c3)
        : "r"(ua0), "r"(ua1), "r"(ua2), "r"(ua3), "r"(ub0), "r"(ub1));
}

// Fragment-order smem stores (values already tf32-rounded by producers).
template<int KSTEPS>
__device__ __forceinline__ void st_afrag_raw(float* F, int m, int k, float4 v) {
    float* dst = F + (((m >> 4) * KSTEPS + (k >> 3)) * 32 + (m & 7) * 4 + (k & 3)) * 4
                   + ((m >> 3) & 1) + (((k >> 2) & 1) << 1);
    dst[0]  = v.x;
    dst[4]  = v.y;
    dst[8]  = v.z;
    dst[12] = v.w;
}
template<int KSTEPS>
__device__ __forceinline__ void st_bfrag_raw(float* F, int r, int d, float4 v) {
    float* dst = F + (((r >> 3) * KSTEPS + (d >> 3)) * 32 + (r & 7) * 4 + (d & 3)) * 2
                   + ((d >> 2) & 1);
    dst[0] = v.x;
    dst[2] = v.y;
    dst[4] = v.z;
    dst[6] = v.w;
}

// ---------------------------------------------------------------------------
// tf32 tensor-core GEMM (proven): C[M,N] = A[M,K] @ B[K,N].
// round_out != 0 -> store tf32-rounded results (for attention inputs).
// ---------------------------------------------------------------------------
constexpr int AS_STRIDE = 20;
constexpr int BS_STRIDE = 136;

__global__ void __launch_bounds__(256)
tf32_gemm_kernel(const float* __restrict__ A, const float* __restrict__ B,
                 float* __restrict__ C, int M, int N, int K, int round_out)
{
    __shared__ float As[2][128][AS_STRIDE];
    __shared__ float Bs[2][16][BS_STRIDE];

    const int tid  = threadIdx.x;
    const int lane = tid & 31;
    const int warp = tid >> 5;
    const int qid  = lane >> 2;
    const int rid  = lane & 3;
    const int wr   = (warp >> 2) * 64;
    const int wc   = (warp & 3) * 32;

    const int rowBase = blockIdx.y * 128;
    const int colBase = blockIdx.x * 128;

    const int ar0 = tid >> 2;
    const int ar1 = ar0 + 64;
    const int ac  = (tid & 3) * 4;
    const int bk0 = tid >> 5;
    const int bk1 = bk0 + 8;
    const int bn  = (tid & 31) * 4;
    const int gn  = colBase + bn;
    const bool bok = (gn < N);

    float acc[4][4][4];
#pragma unroll
    for (int i = 0; i < 4; i++)
#pragma unroll
        for (int j = 0; j < 4; j++)
#pragma unroll
            for (int c = 0; c < 4; c++) acc[i][j][c] = 0.f;

    const int nt = K / 16;
    float4 ra0, ra1, rb0, rb1;

    ra0 = *(const float4*)&A[(size_t)(rowBase + ar0) * K + ac];
    ra1 = *(const float4*)&A[(size_t)(rowBase + ar1) * K + ac];
    rb0 = bok ? *(const float4*)&B[(size_t)bk0 * N + gn] : make_float4(0,0,0,0);
    rb1 = bok ? *(const float4*)&B[(size_t)bk1 * N + gn] : make_float4(0,0,0,0);
    *(float4*)&As[0][ar0][ac] = to_tf32x4(ra0);
    *(float4*)&As[0][ar1][ac] = to_tf32x4(ra1);
    *(float4*)&Bs[0][bk0][bn] = to_tf32x4(rb0);
    *(float4*)&Bs[0][bk1][bn] = to_tf32x4(rb1);
    __syncthreads();

    for (int t = 0; t < nt; t++) {
        const int buf = t & 1;

        if (t + 1 < nt) {
            const int k0 = (t + 1) * 16;
            ra0 = *(const float4*)&A[(size_t)(rowBase + ar0) * K + k0 + ac];
            ra1 = *(const float4*)&A[(size_t)(rowBase + ar1) * K + k0 + ac];
            rb0 = bok ? *(const float4*)&B[(size_t)(k0 + bk0) * N + gn] : make_float4(0,0,0,0);
            rb1 = bok ? *(const float4*)&B[(size_t)(k0 + bk1) * N + gn] : make_float4(0,0,0,0);
        }

#pragma unroll
        for (int ks = 0; ks < 16; ks += 8) {
            float a[4][4], b[4][2];
#pragma unroll
            for (int i = 0; i < 4; i++) {
                const float* p0 = &As[buf][wr + i * 16 + qid][ks + rid];
                const float* p1 = &As[buf][wr + i * 16 + qid + 8][ks + rid];
                a[i][0] = p0[0];
                a[i][1] = p1[0];
                a[i][2] = p0[4];
                a[i][3] = p1[4];
            }
#pragma unroll
            for (int j = 0; j < 4; j++) {
                b[j][0] = Bs[buf][ks + rid][wc + j * 8 + qid];
                b[j][1] = Bs[buf][ks + rid + 4][wc + j * 8 + qid];
            }
#pragma unroll
            for (int i = 0; i < 4; i++)
#pragma unroll
                for (int j = 0; j < 4; j++)
                    mma_tf32(acc[i][j][0], acc[i][j][1], acc[i][j][2], acc[i][j][3],
                             a[i][0], a[i][1], a[i][2], a[i][3],
                             b[j][0], b[j][1]);
        }

        if (t + 1 < nt) {
            const int nb = (t + 1) & 1;
            *(float4*)&As[nb][ar0][ac] = to_tf32x4(ra0);
            *(float4*)&As[nb][ar1][ac] = to_tf32x4(ra1);
            *(float4*)&Bs[nb][bk0][bn] = to_tf32x4(rb0);
            *(float4*)&Bs[nb][bk1][bn] = to_tf32x4(rb1);
        }
        __syncthreads();
    }

#pragma unroll
    for (int i = 0; i < 4; i++) {
        const int r0 = rowBase + wr + i * 16 + qid;
#pragma unroll
        for (int j = 0; j < 4; j++) {
            const int col = colBase + wc + j * 8 + rid * 2;
            if (col < N) {
                float2 v0 = make_float2(acc[i][j][0], acc[i][j][1]);
                float2 v1 = make_float2(acc[i][j][2], acc[i][j][3]);
                if (round_out) {
                    v0.x = to_tf32(v0.x); v0.y = to_tf32(v0.y);
                    v1.x = to_tf32(v1.x); v1.y = to_tf32(v1.y);
                }
                *(float2*)&C[(size_t)r0 * N + col]       = v0;
                *(float2*)&C[(size_t)(r0 + 8) * N + col] = v1;
            }
        }
    }
}

// ---------------------------------------------------------------------------
// RMSNorm (in place)
// ---------------------------------------------------------------------------
__global__ void rmsnorm_kernel(float* __restrict__ x,
                               const float* __restrict__ scale, int D)
{
    __shared__ float red[32];
    float* p = x + (size_t)blockIdx.x * D;

    float ss = 0.f;
    for (int d = threadIdx.x; d < D; d += blockDim.x) {
        float v = p[d];
        ss += v * v;
    }
#pragma unroll
    for (int o = 16; o; o >>= 1) ss += __shfl_xor_sync(0xffffffffu, ss, o);
    if ((threadIdx.x & 31) == 0) red[threadIdx.x >> 5] = ss;
    __syncthreads();
    if (threadIdx.x < 32) {
        float v = (threadIdx.x < (blockDim.x >> 5)) ? red[threadIdx.x] : 0.f;
#pragma unroll
        for (int o = 16; o; o >>= 1) v += __shfl_xor_sync(0xffffffffu, v, o);
        if (threadIdx.x == 0) red[0] = v;
    }
    __syncthreads();
    float inv = rsqrtf(red[0] / (float)D + EPS);
    for (int d = threadIdx.x; d < D; d += blockDim.x)
        p[d] = p[d] * inv * scale[d];
}

// ---------------------------------------------------------------------------
// RoPE tables / application (rope outputs tf32-rounded: consumed only by mma)
// ---------------------------------------------------------------------------
__global__ void rope_table_kernel(float* __restrict__ ctab, float* __restrict__ stab)
{
    int idx = blockIdx.x * blockDim.x + threadIdx.x;
    if (idx >= S * (ROPE / 2)) return;
    int i = idx % (ROPE / 2);
    int s = idx / (ROPE / 2);
    float freq = (float)pow(10000.0, -((double)(2 * i)) / (double)ROPE);
    float ang  = (float)s * freq;
    double a   = (double)ang;
    ctab[idx] = (float)cos(a);
    stab[idx] = (float)sin(a);
}

__global__ void rope_q_kernel(float* __restrict__ q,
                              const float* __restrict__ ctab,
                              const float* __restrict__ stab)
{
    int idx = blockIdx.x * blockDim.x + threadIdx.x;
    if (idx >= T * NH * (ROPE / 2)) return;
    int i   = idx & 31;
    int rem = idx >> 5;
    int h   = rem & (NH - 1);
    int tok = rem >> 4;
    int s   = tok & (S - 1);
    float c  = ctab[s * 32 + i];
    float sn = stab[s * 32 + i];
    float* p = q + (size_t)tok * (NH * ROPE) + h * ROPE + 2 * i;
    float x1 = p[0], x2 = p[1];
    p[0] = to_tf32(x1 * c - x2 * sn);
    p[1] = to_tf32(x1 * sn + x2 * c);
}

__global__ void rope_k_kernel(float* __restrict__ k,
                              const float* __restrict__ ctab,
                              const float* __restrict__ stab)
{
    int idx = blockIdx.x * blockDim.x + threadIdx.x;
    if (idx >= T * (ROPE / 2)) return;
    int i   = idx & 31;
    int tok = idx >> 5;
    int s   = tok & (S - 1);
    float c  = ctab[s * 32 + i];
    float sn = stab[s * 32 + i];
    float* p = k + (size_t)tok * ROPE + 2 * i;
    float x1 = p[0], x2 = p[1];
    p[0] = to_tf32((x1 * c - x2 * sn) * 0.0625f);   // /NH folded in
    p[1] = to_tf32((x1 * sn + x2 * c) * 0.0625f);
}

// ---------------------------------------------------------------------------
// Flash attention: BQ=128, 512 threads (round-8 config) + conflict-free
// strided softmax mapping + exp2-domain logits.
// ---------------------------------------------------------------------------
constexpr int BQ  = 128;
constexpr int BKT = 64;
constexpr int VSTR = 136;
constexpr int PSTR = 68;

struct AttnSmem {
    float Qf[8 * 24 * 32 * 4];
    float Kf[8 * 24 * 32 * 2];
    float V[BKT][VSTR];
    float P[BQ][PSTR];
    float alpha[BQ];
    float invl[BQ];
};

__global__ void __launch_bounds__(512)
attn_kernel(const float* __restrict__ qn, const float* __restrict__ qr,
            const float* __restrict__ kn, const float* __restrict__ kr,
            const float* __restrict__ v,  float* __restrict__ out)
{
    extern __shared__ char smraw[];
    AttnSmem& sm = *reinterpret_cast<AttnSmem*>(smraw);

    const int qt = (gridDim.x - 1) - blockIdx.x;   // heavy blocks first
    const int h  = blockIdx.y;
    const int b  = blockIdx.z;
    const int tid = threadIdx.x;
    const int lane = tid & 31;
    const int warp = tid >> 5;
    const int qid  = lane >> 2;
    const int rid  = lane & 3;
    const int qb = b * S + qt * BQ;

    const int mtile = warp & 7;
    const int ntb   = (warp >> 3) * 4;
    const int row0 = mtile * 16 + qid;
    const int nbv  = (warp >> 3) * 64;

    // per-thread staging indices (fixed)
    const int krn[4] = { tid >> 5, (tid + 512) >> 5, (tid + 1024) >> 5, (tid + 1536) >> 5 };
    const int kcn    = (tid & 31) * 4;
    const int krr[2] = { tid >> 4, (tid + 512) >> 4 };
    const int kcr    = (tid & 15) * 4;

    // ---- stage Q tile [128 x 192] into fragment layout ----
    for (int idx = tid; idx < BQ * 32; idx += 512) {
        int r = idx >> 5, dq = (idx & 31) * 4;
        st_afrag_raw<24>(sm.Qf, r, dq,
            *(const float4*)&qn[(size_t)(qb + r) * (NH * NOPE) + h * NOPE + dq]);
    }
    for (int idx = tid; idx < BQ * 16; idx += 512) {
        int r = idx >> 4, dq = (idx & 15) * 4;
        st_afrag_raw<24>(sm.Qf, r, 128 + dq,
            *(const float4*)&qr[(size_t)(qb + r) * (NH * ROPE) + h * ROPE + dq]);
    }

    const int srow = tid >> 2, squad = tid & 3;

    float m = -1e30f, l = 0.f;    // m in log2 domain
    float acc[8][4];
#pragma unroll
    for (int j = 0; j < 8; j++)
#pragma unroll
        for (int c = 0; c < 4; c++) acc[j][c] = 0.f;

    const int nkt = 2 * qt + 2;

    // ---- prefetch tile 0 into registers ----
    float4 kb[6], vb[4];
    {
        const int kbT = b * S;
#pragma unroll
        for (int i = 0; i < 4; i++)
            kb[i] = *(const float4*)&kn[(size_t)(kbT + krn[i]) * (NH * NOPE) + h * NOPE + kcn];
#pragma unroll
        for (int i = 0; i < 2; i++)
            kb[4 + i] = *(const float4*)&kr[(size_t)(kbT + krr[i]) * ROPE + kcr];
#pragma unroll
        for (int i = 0; i < 4; i++)
            vb[i] = *(const float4*)&v[(size_t)(kbT + krn[i]) * (NH * VD) + h * VD + kcn];
    }

    for (int kt = 0; kt < nkt; kt++) {
        __syncthreads();   // Kf/V free (prev QK/PV done) and Q staging visible

        // ---- store prefetched tile to smem ----
#pragma unroll
        for (int i = 0; i < 4; i++) st_bfrag_raw<24>(sm.Kf, krn[i], kcn, kb[i]);
#pragma unroll
        for (int i = 0; i < 2; i++) st_bfrag_raw<24>(sm.Kf, krr[i], 128 + kcr, kb[4 + i]);
#pragma unroll
        for (int i = 0; i < 4; i++) *(float4*)&sm.V[krn[i]][kcn] = vb[i];
        __syncthreads();   // tile kt ready

        // ---- issue prefetch for tile kt+1 (latency hidden under compute) ----
        if (kt + 1 < nkt) {
            const int kbT = b * S + (kt + 1) * BKT;
#pragma unroll
            for (int i = 0; i < 4; i++)
                kb[i] = *(const float4*)&kn[(size_t)(kbT + krn[i]) * (NH * NOPE) + h * NOPE + kcn];
#pragma unroll
            for (int i = 0; i < 2; i++)
                kb[4 + i] = *(const float4*)&kr[(size_t)(kbT + krr[i]) * ROPE + kcr];
#pragma unroll
            for (int i = 0; i < 4; i++)
                vb[i] = *(const float4*)&v[(size_t)(kbT + krn[i]) * (NH * VD) + h * VD + kcn];
        }

        // ---- scores via tf32 mma (written in log2 domain) ----
        {
            float c[4][4];
#pragma unroll
            for (int j = 0; j < 4; j++)
#pragma unroll
                for (int cc = 0; cc < 4; cc++) c[j][cc] = 0.f;

#pragma unroll
            for (int ks = 0; ks < 24; ks++) {
                float4 a = *(const float4*)&sm.Qf[((mtile * 24 + ks) * 32 + lane) * 4];
#pragma unroll
                for (int j = 0; j < 4; j++) {
                    float2 bb = *(const float2*)&sm.Kf[(((ntb + j) * 24 + ks) * 32 + lane) * 2];
                    mma_tf32(c[j][0], c[j][1], c[j][2], c[j][3],
                             a.x, a.y, a.z, a.w, bb.x, bb.y);
                }
            }

            const bool diag = (kt >= 2 * qt);
            const int r0 = mtile * 16 + qid;
#pragma unroll
            for (int j = 0; j < 4; j++) {
                int col = (ntb + j) * 8 + rid * 2;
                int ki0 = kt * BKT + col;
                float s0 = c[j][0] * SM_SCALE2, s1 = c[j][1] * SM_SCALE2;
                float s2 = c[j][2] * SM_SCALE2, s3 = c[j][3] * SM_SCALE2;
                if (diag) {
                    int qi0 = qt * BQ + r0;
                    int qi1 = qi0 + 8;
                    if (ki0     > qi0) s0 = MASK2;
                    if (ki0 + 1 > qi0) s1 = MASK2;
                    if (ki0     > qi1) s2 = MASK2;
                    if (ki0 + 1 > qi1) s3 = MASK2;
                }
                *(float2*)&sm.P[r0][col]     = make_float2(s0, s1);
                *(float2*)&sm.P[r0 + 8][col] = make_float2(s2, s3);
            }
        }
        __syncthreads();

        // ---- online softmax: strided cols (conflict-free), exp2 domain ----
        {
            float sv[16];
            float tmax = -1e30f;
#pragma unroll
            for (int jj = 0; jj < 16; jj++) {
                sv[jj] = sm.P[srow][jj * 4 + squad];
                tmax = fmaxf(tmax, sv[jj]);
            }
            tmax = fmaxf(tmax, __shfl_xor_sync(0xffffffffu, tmax, 1));
            tmax = fmaxf(tmax, __shfl_xor_sync(0xffffffffu, tmax, 2));
            float mnew = fmaxf(m, tmax);
            float al   = exp2f(m - mnew);
            float ps = 0.f;
#pragma unroll
            for (int jj = 0; jj < 16; jj++) {
                float p = exp2f(sv[jj] - mnew);
                sm.P[srow][jj * 4 + squad] = to_tf32(p);
                ps += p;
            }
            ps += __shfl_xor_sync(0xffffffffu, ps, 1);
            ps += __shfl_xor_sync(0xffffffffu, ps, 2);
            l = l * al + ps;
            m = mnew;
            if (squad == 0) sm.alpha[srow] = al;
        }
        __syncthreads();

        // ---- O = O*alpha + P @ V via tf32 mma ----
        {
            const float al0 = sm.alpha[row0];
            const float al1 = sm.alpha[row0 + 8];
#pragma unroll
            for (int j = 0; j < 8; j++) {
                acc[j][0] *= al0; acc[j][1] *= al0;
                acc[j][2] *= al1; acc[j][3] *= al1;
            }
#pragma unroll
            for (int ks = 0; ks < 8; ks++) {
                const float a0 = sm.P[row0]    [ks * 8 + rid];
                const float a1 = sm.P[row0 + 8][ks * 8 + rid];
                const float a2 = sm.P[row0]    [ks * 8 + rid + 4];
                const float a3 = sm.P[row0 + 8][ks * 8 + rid + 4];
#pragma unroll
                for (int j = 0; j < 8; j++) {
                    const float b0 = sm.V[ks * 8 + rid]    [nbv + j * 8 + qid];
                    const float b1 = sm.V[ks * 8 + rid + 4][nbv + j * 8 + qid];
                    mma_tf32(acc[j][0], acc[j][1], acc[j][2], acc[j][3],
                             a0, a1, a2, a3, b0, b1);
                }
            }
        }
    }

    if (squad == 0) sm.invl[srow] = 1.f / l;
    __syncthreads();

    // ---- epilogue ----
    {
        const float il0 = sm.invl[row0];
        const float il1 = sm.invl[row0 + 8];
        const int tok0 = qb + row0;
        const int tok1 = tok0 + 8;
#pragma unroll
        for (int j = 0; j < 8; j++) {
            const int col = nbv + j * 8 + rid * 2;
            *(float2*)&out[(size_t)tok0 * (NH * VD) + h * VD + col] =
                make_float2(acc[j][0] * il0, acc[j][1] * il0);
            *(float2*)&out[(size_t)tok1 * (NH * VD) + h * VD + col] =
                make_float2(acc[j][2] * il1, acc[j][3] * il1);
        }
    }
}

// ---------------------------------------------------------------------------
// Launch
// ---------------------------------------------------------------------------
static void launch_gemm(const float* A, const float* B, float* C,
                        int M, int N, int K, int round_out = 0)
{
    dim3 grid((N + 127) / 128, (M + 127) / 128);
    tf32_gemm_kernel<<<grid, 256>>>(A, B, C, M, N, K, round_out);
}

extern "C" void kernel_launch(void* const* d_in, const int* in_sizes, int n_in,
                              void* d_out, int out_size)
{
    const float* x         = (const float*)d_in[0];
    const float* W_cq      = (const float*)d_in[1];
    const float* q_scale   = (const float*)d_in[2];
    const float* W_dq_nope = (const float*)d_in[3];
    const float* W_dq_rope = (const float*)d_in[4];
    const float* W_ckv     = (const float*)d_in[5];
    const float* kv_scale  = (const float*)d_in[6];
    const float* W_dk_nope = (const float*)d_in[7];
    const float* W_dv      = (const float*)d_in[8];
    const float* W_krope   = (const float*)d_in[9];
    const float* W_o       = (const float*)d_in[10];
    float* out = (float*)d_out;

    float *cq, *qn, *qr, *ckv, *kn, *vv, *kr, *att, *ctab, *stab;
    cudaGetSymbolAddress((void**)&cq,  g_cq);
    cudaGetSymbolAddress((void**)&qn,  g_qnope);
    cudaGetSymbolAddress((void**)&qr,  g_qrope);
    cudaGetSymbolAddress((void**)&ckv, g_ckv);
    cudaGetSymbolAddress((void**)&kn,  g_knope);
    cudaGetSymbolAddress((void**)&vv,  g_v);
    cudaGetSymbolAddress((void**)&kr,  g_krope);
    cudaGetSymbolAddress((void**)&att, g_attn);
    cudaGetSymbolAddress((void**)&ctab, g_ctab);
    cudaGetSymbolAddress((void**)&stab, g_stab);

    // RoPE tables
    rope_table_kernel<<<(S * 32 + 255) / 256, 256>>>(ctab, stab);

    // Q path
    launch_gemm(x, W_cq, cq, T, QR, H);
    rmsnorm_kernel<<<T, 256>>>(cq, q_scale, QR);
    launch_gemm(cq, W_dq_nope, qn, T, NH * NOPE, QR, 1);   // tf32-rounded out
    launch_gemm(cq, W_dq_rope, qr, T, NH * ROPE, QR);
    rope_q_kernel<<<(T * NH * 32 + 255) / 256, 256>>>(qr, ctab, stab);

    // KV path
    launch_gemm(x, W_ckv, ckv, T, KVR, H);
    rmsnorm_kernel<<<T, 256>>>(ckv, kv_scale, KVR);
    launch_gemm(ckv, W_dk_nope, kn, T, NH * NOPE, KVR, 1); // tf32-rounded out
    launch_gemm(ckv, W_dv, vv, T, NH * VD, KVR, 1);        // tf32-rounded out
    launch_gemm(x, W_krope, kr, T, ROPE, H);
    rope_k_kernel<<<(T * 32 + 255) / 256, 256>>>(kr, ctab, stab);

    // Attention
    cudaFuncSetAttribute((const void*)attn_kernel,
                         cudaFuncAttributeMaxDynamicSharedMemorySize,
                         (int)sizeof(AttnSmem));
    attn_kernel<<<dim3(S / BQ, NH, BB), 512, sizeof(AttnSmem)>>>(qn, qr, kn, kr, vv, att);

    // Output projection
    launch_gemm(att, W_o, out, T, H, NH * VD);
}

// round 11
// speedup vs baseline: 1.2684x; 1.1511x over previous
#include <cuda_runtime.h>
#include <math.h>
#include <stdint.h>

// ---------------------------------------------------------------------------
// Problem constants
// ---------------------------------------------------------------------------
constexpr int H    = 2048;
constexpr int NH   = 16;
constexpr int NOPE = 128;
constexpr int ROPE = 64;
constexpr int VD   = 128;
constexpr int QR   = 1024;
constexpr int KVR  = 512;
constexpr int BB   = 2;       // batch
constexpr int S    = 2048;    // seq len
constexpr int T    = BB * S;  // 4096 tokens
constexpr float EPS = 1e-6f;
constexpr float SM_SCALE = 0.07216878364870323f;          // 1/sqrt(192)
constexpr float SM_SCALE2 = 0.10412105626079532f;         // SM_SCALE * log2(e)
constexpr float MASK2 = -1.4426950408889634e9f;           // -1e9 * log2(e)

// ---------------------------------------------------------------------------
// Device scratch (allocation-free rule: __device__ globals)
// ---------------------------------------------------------------------------
__device__ float g_cq   [T * QR];
__device__ float g_qnope[T * NH * NOPE];
__device__ float g_qrope[T * NH * ROPE];
__device__ float g_ckv  [T * KVR];
__device__ float g_knope[T * NH * NOPE];
__device__ float g_v    [T * NH * VD];
__device__ float g_krope[T * ROPE];
__device__ float g_attn [T * NH * VD];
__device__ float g_ctab [S * (ROPE / 2)];
__device__ float g_stab [S * (ROPE / 2)];

// ---------------------------------------------------------------------------
// tf32 helpers
// ---------------------------------------------------------------------------
__device__ __forceinline__ float to_tf32(float x) {
    uint32_t u;
    asm("cvt.rna.tf32.f32 %0, %1;" : "=r"(u) : "f"(x));
    return __uint_as_float(u);
}
__device__ __forceinline__ float4 to_tf32x4(float4 v) {
    return make_float4(to_tf32(v.x), to_tf32(v.y), to_tf32(v.z), to_tf32(v.w));
}

__device__ __forceinline__ void mma_tf32(float& c0, float& c1, float& c2, float& c3,
                                         float a0, float a1, float a2, float a3,
                                         float b0, float b1)
{
    uint32_t ua0 = __float_as_uint(a0), ua1 = __float_as_uint(a1);
    uint32_t ua2 = __float_as_uint(a2), ua3 = __float_as_uint(a3);
    uint32_t ub0 = __float_as_uint(b0), ub1 = __float_as_uint(b1);
    asm volatile(
        "mma.sync.aligned.m16n8k8.row.col.f32.tf32.tf32.f32 "
        "{%0,%1,%2,%3}, {%4,%5,%6,%7}, {%8,%9}, {%0,%1,%2,%3};\n"
        : "+f"(c0), "+f"(c1), "+f"(c2), "+f"(c3)
        : "r"(ua0), "r"(ua1), "r"(ua2), "r"(ua3), "r"(ub0), "r"(ub1));
}

// Fragment-order smem stores (values already tf32-rounded by producers).
template<int KSTEPS>
__device__ __forceinline__ void st_afrag_raw(float* F, int m, int k, float4 v) {
    float* dst = F + (((m >> 4) * KSTEPS + (k >> 3)) * 32 + (m & 7) * 4 + (k & 3)) * 4
                   + ((m >> 3) & 1) + (((k >> 2) & 1) << 1);
    dst[0]  = v.x;
    dst[4]  = v.y;
    dst[8]  = v.z;
    dst[12] = v.w;
}
template<int KSTEPS>
__device__ __forceinline__ void st_bfrag_raw(float* F, int r, int d, float4 v) {
    float* dst = F + (((r >> 3) * KSTEPS + (d >> 3)) * 32 + (r & 7) * 4 + (d & 3)) * 2
                   + ((d >> 2) & 1);
    dst[0] = v.x;
    dst[2] = v.y;
    dst[4] = v.z;
    dst[6] = v.w;
}

// ---------------------------------------------------------------------------
// tf32 tensor-core GEMM (proven): C[M,N] = A[M,K] @ B[K,N].
// round_out != 0 -> store tf32-rounded results (for attention inputs).
// ---------------------------------------------------------------------------
constexpr int AS_STRIDE = 20;
constexpr int BS_STRIDE = 136;

__global__ void __launch_bounds__(256)
tf32_gemm_kernel(const float* __restrict__ A, const float* __restrict__ B,
                 float* __restrict__ C, int M, int N, int K, int round_out)
{
    __shared__ float As[2][128][AS_STRIDE];
    __shared__ float Bs[2][16][BS_STRIDE];

    const int tid  = threadIdx.x;
    const int lane = tid & 31;
    const int warp = tid >> 5;
    const int qid  = lane >> 2;
    const int rid  = lane & 3;
    const int wr   = (warp >> 2) * 64;
    const int wc   = (warp & 3) * 32;

    const int rowBase = blockIdx.y * 128;
    const int colBase = blockIdx.x * 128;

    const int ar0 = tid >> 2;
    const int ar1 = ar0 + 64;
    const int ac  = (tid & 3) * 4;
    const int bk0 = tid >> 5;
    const int bk1 = bk0 + 8;
    const int bn  = (tid & 31) * 4;
    const int gn  = colBase + bn;
    const bool bok = (gn < N);

    float acc[4][4][4];
#pragma unroll
    for (int i = 0; i < 4; i++)
#pragma unroll
        for (int j = 0; j < 4; j++)
#pragma unroll
            for (int c = 0; c < 4; c++) acc[i][j][c] = 0.f;

    const int nt = K / 16;
    float4 ra0, ra1, rb0, rb1;

    ra0 = *(const float4*)&A[(size_t)(rowBase + ar0) * K + ac];
    ra1 = *(const float4*)&A[(size_t)(rowBase + ar1) * K + ac];
    rb0 = bok ? *(const float4*)&B[(size_t)bk0 * N + gn] : make_float4(0,0,0,0);
    rb1 = bok ? *(const float4*)&B[(size_t)bk1 * N + gn] : make_float4(0,0,0,0);
    *(float4*)&As[0][ar0][ac] = to_tf32x4(ra0);
    *(float4*)&As[0][ar1][ac] = to_tf32x4(ra1);
    *(float4*)&Bs[0][bk0][bn] = to_tf32x4(rb0);
    *(float4*)&Bs[0][bk1][bn] = to_tf32x4(rb1);
    __syncthreads();

    for (int t = 0; t < nt; t++) {
        const int buf = t & 1;

        if (t + 1 < nt) {
            const int k0 = (t + 1) * 16;
            ra0 = *(const float4*)&A[(size_t)(rowBase + ar0) * K + k0 + ac];
            ra1 = *(const float4*)&A[(size_t)(rowBase + ar1) * K + k0 + ac];
            rb0 = bok ? *(const float4*)&B[(size_t)(k0 + bk0) * N + gn] : make_float4(0,0,0,0);
            rb1 = bok ? *(const float4*)&B[(size_t)(k0 + bk1) * N + gn] : make_float4(0,0,0,0);
        }

#pragma unroll
        for (int ks = 0; ks < 16; ks += 8) {
            float a[4][4], b[4][2];
#pragma unroll
            for (int i = 0; i < 4; i++) {
                const float* p0 = &As[buf][wr + i * 16 + qid][ks + rid];
                const float* p1 = &As[buf][wr + i * 16 + qid + 8][ks + rid];
                a[i][0] = p0[0];
                a[i][1] = p1[0];
                a[i][2] = p0[4];
                a[i][3] = p1[4];
            }
#pragma unroll
            for (int j = 0; j < 4; j++) {
                b[j][0] = Bs[buf][ks + rid][wc + j * 8 + qid];
                b[j][1] = Bs[buf][ks + rid + 4][wc + j * 8 + qid];
            }
#pragma unroll
            for (int i = 0; i < 4; i++)
#pragma unroll
                for (int j = 0; j < 4; j++)
                    mma_tf32(acc[i][j][0], acc[i][j][1], acc[i][j][2], acc[i][j][3],
                             a[i][0], a[i][1], a[i][2], a[i][3],
                             b[j][0], b[j][1]);
        }

        if (t + 1 < nt) {
            const int nb = (t + 1) & 1;
            *(float4*)&As[nb][ar0][ac] = to_tf32x4(ra0);
            *(float4*)&As[nb][ar1][ac] = to_tf32x4(ra1);
            *(float4*)&Bs[nb][bk0][bn] = to_tf32x4(rb0);
            *(float4*)&Bs[nb][bk1][bn] = to_tf32x4(rb1);
        }
        __syncthreads();
    }

#pragma unroll
    for (int i = 0; i < 4; i++) {
        const int r0 = rowBase + wr + i * 16 + qid;
#pragma unroll
        for (int j = 0; j < 4; j++) {
            const int col = colBase + wc + j * 8 + rid * 2;
            if (col < N) {
                float2 v0 = make_float2(acc[i][j][0], acc[i][j][1]);
                float2 v1 = make_float2(acc[i][j][2], acc[i][j][3]);
                if (round_out) {
                    v0.x = to_tf32(v0.x); v0.y = to_tf32(v0.y);
                    v1.x = to_tf32(v1.x); v1.y = to_tf32(v1.y);
                }
                *(float2*)&C[(size_t)r0 * N + col]       = v0;
                *(float2*)&C[(size_t)(r0 + 8) * N + col] = v1;
            }
        }
    }
}

// ---------------------------------------------------------------------------
// RMSNorm (in place)
// ---------------------------------------------------------------------------
__global__ void rmsnorm_kernel(float* __restrict__ x,
                               const float* __restrict__ scale, int D)
{
    __shared__ float red[32];
    float* p = x + (size_t)blockIdx.x * D;

    float ss = 0.f;
    for (int d = threadIdx.x; d < D; d += blockDim.x) {
        float v = p[d];
        ss += v * v;
    }
#pragma unroll
    for (int o = 16; o; o >>= 1) ss += __shfl_xor_sync(0xffffffffu, ss, o);
    if ((threadIdx.x & 31) == 0) red[threadIdx.x >> 5] = ss;
    __syncthreads();
    if (threadIdx.x < 32) {
        float v = (threadIdx.x < (blockDim.x >> 5)) ? red[threadIdx.x] : 0.f;
#pragma unroll
        for (int o = 16; o; o >>= 1) v += __shfl_xor_sync(0xffffffffu, v, o);
        if (threadIdx.x == 0) red[0] = v;
    }
    __syncthreads();
    float inv = rsqrtf(red[0] / (float)D + EPS);
    for (int d = threadIdx.x; d < D; d += blockDim.x)
        p[d] = p[d] * inv * scale[d];
}

// ---------------------------------------------------------------------------
// RoPE tables / application (rope outputs tf32-rounded: consumed only by mma)
// ---------------------------------------------------------------------------
__global__ void rope_table_kernel(float* __restrict__ ctab, float* __restrict__ stab)
{
    int idx = blockIdx.x * blockDim.x + threadIdx.x;
    if (idx >= S * (ROPE / 2)) return;
    int i = idx % (ROPE / 2);
    int s = idx / (ROPE / 2);
    float freq = (float)pow(10000.0, -((double)(2 * i)) / (double)ROPE);
    float ang  = (float)s * freq;
    double a   = (double)ang;
    ctab[idx] = (float)cos(a);
    stab[idx] = (float)sin(a);
}

__global__ void rope_q_kernel(float* __restrict__ q,
                              const float* __restrict__ ctab,
                              const float* __restrict__ stab)
{
    int idx = blockIdx.x * blockDim.x + threadIdx.x;
    if (idx >= T * NH * (ROPE / 2)) return;
    int i   = idx & 31;
    int rem = idx >> 5;
    int h   = rem & (NH - 1);
    int tok = rem >> 4;
    int s   = tok & (S - 1);
    float c  = ctab[s * 32 + i];
    float sn = stab[s * 32 + i];
    float* p = q + (size_t)tok * (NH * ROPE) + h * ROPE + 2 * i;
    float x1 = p[0], x2 = p[1];
    p[0] = to_tf32(x1 * c - x2 * sn);
    p[1] = to_tf32(x1 * sn + x2 * c);
}

__global__ void rope_k_kernel(float* __restrict__ k,
                              const float* __restrict__ ctab,
                              const float* __restrict__ stab)
{
    int idx = blockIdx.x * blockDim.x + threadIdx.x;
    if (idx >= T * (ROPE / 2)) return;
    int i   = idx & 31;
    int tok = idx >> 5;
    int s   = tok & (S - 1);
    float c  = ctab[s * 32 + i];
    float sn = stab[s * 32 + i];
    float* p = k + (size_t)tok * ROPE + 2 * i;
    float x1 = p[0], x2 = p[1];
    p[0] = to_tf32((x1 * c - x2 * sn) * 0.0625f);   // /NH folded in
    p[1] = to_tf32((x1 * sn + x2 * c) * 0.0625f);
}

// ---------------------------------------------------------------------------
// Flash attention: BQ=128, 512 threads, conflict-free strided softmax,
// exp2-domain logits, register K/V prefetch. (round-10 kernel, unchanged)
// ---------------------------------------------------------------------------
constexpr int BQ  = 128;
constexpr int BKT = 64;
constexpr int VSTR = 136;
constexpr int PSTR = 68;

struct AttnSmem {
    float Qf[8 * 24 * 32 * 4];
    float Kf[8 * 24 * 32 * 2];
    float V[BKT][VSTR];
    float P[BQ][PSTR];
    float alpha[BQ];
    float invl[BQ];
};

__global__ void __launch_bounds__(512)
attn_kernel(const float* __restrict__ qn, const float* __restrict__ qr,
            const float* __restrict__ kn, const float* __restrict__ kr,
            const float* __restrict__ v,  float* __restrict__ out)
{
    extern __shared__ char smraw[];
    AttnSmem& sm = *reinterpret_cast<AttnSmem*>(smraw);

    const int qt = (gridDim.x - 1) - blockIdx.x;   // heavy blocks first
    const int h  = blockIdx.y;
    const int b  = blockIdx.z;
    const int tid = threadIdx.x;
    const int lane = tid & 31;
    const int warp = tid >> 5;
    const int qid  = lane >> 2;
    const int rid  = lane & 3;
    const int qb = b * S + qt * BQ;

    const int mtile = warp & 7;
    const int ntb   = (warp >> 3) * 4;
    const int row0 = mtile * 16 + qid;
    const int nbv  = (warp >> 3) * 64;

    const int krn[4] = { tid >> 5, (tid + 512) >> 5, (tid + 1024) >> 5, (tid + 1536) >> 5 };
    const int kcn    = (tid & 31) * 4;
    const int krr[2] = { tid >> 4, (tid + 512) >> 4 };
    const int kcr    = (tid & 15) * 4;

    for (int idx = tid; idx < BQ * 32; idx += 512) {
        int r = idx >> 5, dq = (idx & 31) * 4;
        st_afrag_raw<24>(sm.Qf, r, dq,
            *(const float4*)&qn[(size_t)(qb + r) * (NH * NOPE) + h * NOPE + dq]);
    }
    for (int idx = tid; idx < BQ * 16; idx += 512) {
        int r = idx >> 4, dq = (idx & 15) * 4;
        st_afrag_raw<24>(sm.Qf, r, 128 + dq,
            *(const float4*)&qr[(size_t)(qb + r) * (NH * ROPE) + h * ROPE + dq]);
    }

    const int srow = tid >> 2, squad = tid & 3;

    float m = -1e30f, l = 0.f;    // m in log2 domain
    float acc[8][4];
#pragma unroll
    for (int j = 0; j < 8; j++)
#pragma unroll
        for (int c = 0; c < 4; c++) acc[j][c] = 0.f;

    const int nkt = 2 * qt + 2;

    float4 kb[6], vb[4];
    {
        const int kbT = b * S;
#pragma unroll
        for (int i = 0; i < 4; i++)
            kb[i] = *(const float4*)&kn[(size_t)(kbT + krn[i]) * (NH * NOPE) + h * NOPE + kcn];
#pragma unroll
        for (int i = 0; i < 2; i++)
            kb[4 + i] = *(const float4*)&kr[(size_t)(kbT + krr[i]) * ROPE + kcr];
#pragma unroll
        for (int i = 0; i < 4; i++)
            vb[i] = *(const float4*)&v[(size_t)(kbT + krn[i]) * (NH * VD) + h * VD + kcn];
    }

    for (int kt = 0; kt < nkt; kt++) {
        __syncthreads();

#pragma unroll
        for (int i = 0; i < 4; i++) st_bfrag_raw<24>(sm.Kf, krn[i], kcn, kb[i]);
#pragma unroll
        for (int i = 0; i < 2; i++) st_bfrag_raw<24>(sm.Kf, krr[i], 128 + kcr, kb[4 + i]);
#pragma unroll
        for (int i = 0; i < 4; i++) *(float4*)&sm.V[krn[i]][kcn] = vb[i];
        __syncthreads();

        if (kt + 1 < nkt) {
            const int kbT = b * S + (kt + 1) * BKT;
#pragma unroll
            for (int i = 0; i < 4; i++)
                kb[i] = *(const float4*)&kn[(size_t)(kbT + krn[i]) * (NH * NOPE) + h * NOPE + kcn];
#pragma unroll
            for (int i = 0; i < 2; i++)
                kb[4 + i] = *(const float4*)&kr[(size_t)(kbT + krr[i]) * ROPE + kcr];
#pragma unroll
            for (int i = 0; i < 4; i++)
                vb[i] = *(const float4*)&v[(size_t)(kbT + krn[i]) * (NH * VD) + h * VD + kcn];
        }

        {
            float c[4][4];
#pragma unroll
            for (int j = 0; j < 4; j++)
#pragma unroll
                for (int cc = 0; cc < 4; cc++) c[j][cc] = 0.f;

#pragma unroll
            for (int ks = 0; ks < 24; ks++) {
                float4 a = *(const float4*)&sm.Qf[((mtile * 24 + ks) * 32 + lane) * 4];
#pragma unroll
                for (int j = 0; j < 4; j++) {
                    float2 bb = *(const float2*)&sm.Kf[(((ntb + j) * 24 + ks) * 32 + lane) * 2];
                    mma_tf32(c[j][0], c[j][1], c[j][2], c[j][3],
                             a.x, a.y, a.z, a.w, bb.x, bb.y);
                }
            }

            const bool diag = (kt >= 2 * qt);
            const int r0 = mtile * 16 + qid;
#pragma unroll
            for (int j = 0; j < 4; j++) {
                int col = (ntb + j) * 8 + rid * 2;
                int ki0 = kt * BKT + col;
                float s0 = c[j][0] * SM_SCALE2, s1 = c[j][1] * SM_SCALE2;
                float s2 = c[j][2] * SM_SCALE2, s3 = c[j][3] * SM_SCALE2;
                if (diag) {
                    int qi0 = qt * BQ + r0;
                    int qi1 = qi0 + 8;
                    if (ki0     > qi0) s0 = MASK2;
                    if (ki0 + 1 > qi0) s1 = MASK2;
                    if (ki0     > qi1) s2 = MASK2;
                    if (ki0 + 1 > qi1) s3 = MASK2;
                }
                *(float2*)&sm.P[r0][col]     = make_float2(s0, s1);
                *(float2*)&sm.P[r0 + 8][col] = make_float2(s2, s3);
            }
        }
        __syncthreads();

        {
            float sv[16];
            float tmax = -1e30f;
#pragma unroll
            for (int jj = 0; jj < 16; jj++) {
                sv[jj] = sm.P[srow][jj * 4 + squad];
                tmax = fmaxf(tmax, sv[jj]);
            }
            tmax = fmaxf(tmax, __shfl_xor_sync(0xffffffffu, tmax, 1));
            tmax = fmaxf(tmax, __shfl_xor_sync(0xffffffffu, tmax, 2));
            float mnew = fmaxf(m, tmax);
            float al   = exp2f(m - mnew);
            float ps = 0.f;
#pragma unroll
            for (int jj = 0; jj < 16; jj++) {
                float p = exp2f(sv[jj] - mnew);
                sm.P[srow][jj * 4 + squad] = to_tf32(p);
                ps += p;
            }
            ps += __shfl_xor_sync(0xffffffffu, ps, 1);
            ps += __shfl_xor_sync(0xffffffffu, ps, 2);
            l = l * al + ps;
            m = mnew;
            if (squad == 0) sm.alpha[srow] = al;
        }
        __syncthreads();

        {
            const float al0 = sm.alpha[row0];
            const float al1 = sm.alpha[row0 + 8];
#pragma unroll
            for (int j = 0; j < 8; j++) {
                acc[j][0] *= al0; acc[j][1] *= al0;
                acc[j][2] *= al1; acc[j][3] *= al1;
            }
#pragma unroll
            for (int ks = 0; ks < 8; ks++) {
                const float a0 = sm.P[row0]    [ks * 8 + rid];
                const float a1 = sm.P[row0 + 8][ks * 8 + rid];
                const float a2 = sm.P[row0]    [ks * 8 + rid + 4];
                const float a3 = sm.P[row0 + 8][ks * 8 + rid + 4];
#pragma unroll
                for (int j = 0; j < 8; j++) {
                    const float b0 = sm.V[ks * 8 + rid]    [nbv + j * 8 + qid];
                    const float b1 = sm.V[ks * 8 + rid + 4][nbv + j * 8 + qid];
                    mma_tf32(acc[j][0], acc[j][1], acc[j][2], acc[j][3],
                             a0, a1, a2, a3, b0, b1);
                }
            }
        }
    }

    if (squad == 0) sm.invl[srow] = 1.f / l;
    __syncthreads();

    {
        const float il0 = sm.invl[row0];
        const float il1 = sm.invl[row0 + 8];
        const int tok0 = qb + row0;
        const int tok1 = tok0 + 8;
#pragma unroll
        for (int j = 0; j < 8; j++) {
            const int col = nbv + j * 8 + rid * 2;
            *(float2*)&out[(size_t)tok0 * (NH * VD) + h * VD + col] =
                make_float2(acc[j][0] * il0, acc[j][1] * il0);
            *(float2*)&out[(size_t)tok1 * (NH * VD) + h * VD + col] =
                make_float2(acc[j][2] * il1, acc[j][3] * il1);
        }
    }
}

// ---------------------------------------------------------------------------
// Launch (Q path and KV path forked onto concurrent streams inside capture)
// ---------------------------------------------------------------------------
static void launch_gemm_s(cudaStream_t s, const float* A, const float* B, float* C,
                          int M, int N, int K, int round_out = 0)
{
    dim3 grid((N + 127) / 128, (M + 127) / 128);
    tf32_gemm_kernel<<<grid, 256, 0, s>>>(A, B, C, M, N, K, round_out);
}

extern "C" void kernel_launch(void* const* d_in, const int* in_sizes, int n_in,
                              void* d_out, int out_size)
{
    const float* x         = (const float*)d_in[0];
    const float* W_cq      = (const float*)d_in[1];
    const float* q_scale   = (const float*)d_in[2];
    const float* W_dq_nope = (const float*)d_in[3];
    const float* W_dq_rope = (const float*)d_in[4];
    const float* W_ckv     = (const float*)d_in[5];
    const float* kv_scale  = (const float*)d_in[6];
    const float* W_dk_nope = (const float*)d_in[7];
    const float* W_dv      = (const float*)d_in[8];
    const float* W_krope   = (const float*)d_in[9];
    const float* W_o       = (const float*)d_in[10];
    float* out = (float*)d_out;

    float *cq, *qn, *qr, *ckv, *kn, *vv, *kr, *att, *ctab, *stab;
    cudaGetSymbolAddress((void**)&cq,  g_cq);
    cudaGetSymbolAddress((void**)&qn,  g_qnope);
    cudaGetSymbolAddress((void**)&qr,  g_qrope);
    cudaGetSymbolAddress((void**)&ckv, g_ckv);
    cudaGetSymbolAddress((void**)&kn,  g_knope);
    cudaGetSymbolAddress((void**)&vv,  g_v);
    cudaGetSymbolAddress((void**)&kr,  g_krope);
    cudaGetSymbolAddress((void**)&att, g_attn);
    cudaGetSymbolAddress((void**)&ctab, g_ctab);
    cudaGetSymbolAddress((void**)&stab, g_stab);

    // Fork/join machinery. Host-side creation cost is irrelevant: the harness
    // times GRAPH REPLAYS, where only captured GPU work executes.
    cudaStream_t s0 = 0;           // default (capture) stream
    cudaStream_t skv;
    cudaEvent_t ev_fork, ev_kv;
    cudaStreamCreateWithFlags(&skv, cudaStreamNonBlocking);
    cudaEventCreateWithFlags(&ev_fork, cudaEventDisableTiming);
    cudaEventCreateWithFlags(&ev_kv,  cudaEventDisableTiming);

    // RoPE tables (needed by both paths)
    rope_table_kernel<<<(S * 32 + 255) / 256, 256, 0, s0>>>(ctab, stab);

    // ---- fork: KV path on skv ----
    cudaEventRecord(ev_fork, s0);
    cudaStreamWaitEvent(skv, ev_fork, 0);

    // KV path (skv)
    launch_gemm_s(skv, x, W_krope, kr, T, ROPE, H);
    rope_k_kernel<<<(T * 32 + 255) / 256, 256, 0, skv>>>(kr, ctab, stab);
    launch_gemm_s(skv, x, W_ckv, ckv, T, KVR, H);
    rmsnorm_kernel<<<T, 256, 0, skv>>>(ckv, kv_scale, KVR);
    launch_gemm_s(skv, ckv, W_dk_nope, kn, T, NH * NOPE, KVR, 1); // tf32 out
    launch_gemm_s(skv, ckv, W_dv, vv, T, NH * VD, KVR, 1);        // tf32 out
    cudaEventRecord(ev_kv, skv);

    // Q path (s0)
    launch_gemm_s(s0, x, W_cq, cq, T, QR, H);
    rmsnorm_kernel<<<T, 256, 0, s0>>>(cq, q_scale, QR);
    launch_gemm_s(s0, cq, W_dq_nope, qn, T, NH * NOPE, QR, 1);    // tf32 out
    launch_gemm_s(s0, cq, W_dq_rope, qr, T, NH * ROPE, QR);
    rope_q_kernel<<<(T * NH * 32 + 255) / 256, 256, 0, s0>>>(qr, ctab, stab);

    // ---- join ----
    cudaStreamWaitEvent(s0, ev_kv, 0);

    // Attention
    cudaFuncSetAttribute((const void*)attn_kernel,
                         cudaFuncAttributeMaxDynamicSharedMemorySize,
                         (int)sizeof(AttnSmem));
    attn_kernel<<<dim3(S / BQ, NH, BB), 512, sizeof(AttnSmem), s0>>>(qn, qr, kn, kr, vv, att);

    // Output projection
    launch_gemm_s(s0, att, W_o, out, T, H, NH * VD);
}

// round 12
// speedup vs baseline: 1.2750x; 1.0052x over previous
#include <cuda_runtime.h>
#include <math.h>
#include <stdint.h>

// ---------------------------------------------------------------------------
// Problem constants
// ---------------------------------------------------------------------------
constexpr int H    = 2048;
constexpr int NH   = 16;
constexpr int NOPE = 128;
constexpr int ROPE = 64;
constexpr int VD   = 128;
constexpr int QR   = 1024;
constexpr int KVR  = 512;
constexpr int BB   = 2;       // batch
constexpr int S    = 2048;    // seq len
constexpr int T    = BB * S;  // 4096 tokens
constexpr float EPS = 1e-6f;
constexpr float SM_SCALE = 0.07216878364870323f;          // 1/sqrt(192)
constexpr float SM_SCALE2 = 0.10412105626079532f;         // SM_SCALE * log2(e)
constexpr float MASK2 = -1.4426950408889634e9f;           // -1e9 * log2(e)

// ---------------------------------------------------------------------------
// Device scratch (allocation-free rule: __device__ globals)
// ---------------------------------------------------------------------------
__device__ float g_cq   [T * QR];
__device__ float g_qnope[T * NH * NOPE];
__device__ float g_qrope[T * NH * ROPE];
__device__ float g_ckv  [T * KVR];
__device__ float g_knope[T * NH * NOPE];
__device__ float g_v    [T * NH * VD];
__device__ float g_krope[T * ROPE];
__device__ float g_attn [T * NH * VD];
__device__ float g_ctab [S * (ROPE / 2)];
__device__ float g_stab [S * (ROPE / 2)];

// ---------------------------------------------------------------------------
// tf32 helpers
// ---------------------------------------------------------------------------
__device__ __forceinline__ float to_tf32(float x) {
    uint32_t u;
    asm("cvt.rna.tf32.f32 %0, %1;" : "=r"(u) : "f"(x));
    return __uint_as_float(u);
}
__device__ __forceinline__ float4 to_tf32x4(float4 v) {
    return make_float4(to_tf32(v.x), to_tf32(v.y), to_tf32(v.z), to_tf32(v.w));
}

__device__ __forceinline__ void mma_tf32(float& c0, float& c1, float& c2, float& c3,
                                         float a0, float a1, float a2, float a3,
                                         float b0, float b1)
{
    uint32_t ua0 = __float_as_uint(a0), ua1 = __float_as_uint(a1);
    uint32_t ua2 = __float_as_uint(a2), ua3 = __float_as_uint(a3);
    uint32_t ub0 = __float_as_uint(b0), ub1 = __float_as_uint(b1);
    asm volatile(
        "mma.sync.aligned.m16n8k8.row.col.f32.tf32.tf32.f32 "
        "{%0,%1,%2,%3}, {%4,%5,%6,%7}, {%8,%9}, {%0,%1,%2,%3};\n"
        : "+f"(c0), "+f"(c1), "+f"(c2), "+f"(c3)
        : "r"(ua0), "r"(ua1), "r"(ua2), "r"(ua3), "r"(ub0), "r"(ub1));
}

// Fragment-order smem stores (values already tf32-rounded by producers).
template<int KSTEPS>
__device__ __forceinline__ void st_afrag_raw(float* F, int m, int k, float4 v) {
    float* dst = F + (((m >> 4) * KSTEPS + (k >> 3)) * 32 + (m & 7) * 4 + (k & 3)) * 4
                   + ((m >> 3) & 1) + (((k >> 2) & 1) << 1);
    dst[0]  = v.x;
    dst[4]  = v.y;
    dst[8]  = v.z;
    dst[12] = v.w;
}
template<int KSTEPS>
__device__ __forceinline__ void st_bfrag_raw(float* F, int r, int d, float4 v) {
    float* dst = F + (((r >> 3) * KSTEPS + (d >> 3)) * 32 + (r & 7) * 4 + (d & 3)) * 2
                   + ((d >> 2) & 1);
    dst[0] = v.x;
    dst[2] = v.y;
    dst[4] = v.z;
    dst[6] = v.w;
}

// ---------------------------------------------------------------------------
// tf32 tensor-core GEMM (proven): C[M,N] = A[M,K] @ B[K,N].
// round_out != 0 -> store tf32-rounded results (for attention inputs).
// ---------------------------------------------------------------------------
constexpr int AS_STRIDE = 20;
constexpr int BS_STRIDE = 136;

__global__ void __launch_bounds__(256)
tf32_gemm_kernel(const float* __restrict__ A, const float* __restrict__ B,
                 float* __restrict__ C, int M, int N, int K, int round_out)
{
    __shared__ float As[2][128][AS_STRIDE];
    __shared__ float Bs[2][16][BS_STRIDE];

    const int tid  = threadIdx.x;
    const int lane = tid & 31;
    const int warp = tid >> 5;
    const int qid  = lane >> 2;
    const int rid  = lane & 3;
    const int wr   = (warp >> 2) * 64;
    const int wc   = (warp & 3) * 32;

    const int rowBase = blockIdx.y * 128;
    const int colBase = blockIdx.x * 128;

    const int ar0 = tid >> 2;
    const int ar1 = ar0 + 64;
    const int ac  = (tid & 3) * 4;
    const int bk0 = tid >> 5;
    const int bk1 = bk0 + 8;
    const int bn  = (tid & 31) * 4;
    const int gn  = colBase + bn;
    const bool bok = (gn < N);

    float acc[4][4][4];
#pragma unroll
    for (int i = 0; i < 4; i++)
#pragma unroll
        for (int j = 0; j < 4; j++)
#pragma unroll
            for (int c = 0; c < 4; c++) acc[i][j][c] = 0.f;

    const int nt = K / 16;
    float4 ra0, ra1, rb0, rb1;

    ra0 = *(const float4*)&A[(size_t)(rowBase + ar0) * K + ac];
    ra1 = *(const float4*)&A[(size_t)(rowBase + ar1) * K + ac];
    rb0 = bok ? *(const float4*)&B[(size_t)bk0 * N + gn] : make_float4(0,0,0,0);
    rb1 = bok ? *(const float4*)&B[(size_t)bk1 * N + gn] : make_float4(0,0,0,0);
    *(float4*)&As[0][ar0][ac] = to_tf32x4(ra0);
    *(float4*)&As[0][ar1][ac] = to_tf32x4(ra1);
    *(float4*)&Bs[0][bk0][bn] = to_tf32x4(rb0);
    *(float4*)&Bs[0][bk1][bn] = to_tf32x4(rb1);
    __syncthreads();

    for (int t = 0; t < nt; t++) {
        const int buf = t & 1;

        if (t + 1 < nt) {
            const int k0 = (t + 1) * 16;
            ra0 = *(const float4*)&A[(size_t)(rowBase + ar0) * K + k0 + ac];
            ra1 = *(const float4*)&A[(size_t)(rowBase + ar1) * K + k0 + ac];
            rb0 = bok ? *(const float4*)&B[(size_t)(k0 + bk0) * N + gn] : make_float4(0,0,0,0);
            rb1 = bok ? *(const float4*)&B[(size_t)(k0 + bk1) * N + gn] : make_float4(0,0,0,0);
        }

#pragma unroll
        for (int ks = 0; ks < 16; ks += 8) {
            float a[4][4], b[4][2];
#pragma unroll
            for (int i = 0; i < 4; i++) {
                const float* p0 = &As[buf][wr + i * 16 + qid][ks + rid];
                const float* p1 = &As[buf][wr + i * 16 + qid + 8][ks + rid];
                a[i][0] = p0[0];
                a[i][1] = p1[0];
                a[i][2] = p0[4];
                a[i][3] = p1[4];
            }
#pragma unroll
            for (int j = 0; j < 4; j++) {
                b[j][0] = Bs[buf][ks + rid][wc + j * 8 + qid];
                b[j][1] = Bs[buf][ks + rid + 4][wc + j * 8 + qid];
            }
#pragma unroll
            for (int i = 0; i < 4; i++)
#pragma unroll
                for (int j = 0; j < 4; j++)
                    mma_tf32(acc[i][j][0], acc[i][j][1], acc[i][j][2], acc[i][j][3],
                             a[i][0], a[i][1], a[i][2], a[i][3],
                             b[j][0], b[j][1]);
        }

        if (t + 1 < nt) {
            const int nb = (t + 1) & 1;
            *(float4*)&As[nb][ar0][ac] = to_tf32x4(ra0);
            *(float4*)&As[nb][ar1][ac] = to_tf32x4(ra1);
            *(float4*)&Bs[nb][bk0][bn] = to_tf32x4(rb0);
            *(float4*)&Bs[nb][bk1][bn] = to_tf32x4(rb1);
        }
        __syncthreads();
    }

#pragma unroll
    for (int i = 0; i < 4; i++) {
        const int r0 = rowBase + wr + i * 16 + qid;
#pragma unroll
        for (int j = 0; j < 4; j++) {
            const int col = colBase + wc + j * 8 + rid * 2;
            if (col < N) {
                float2 v0 = make_float2(acc[i][j][0], acc[i][j][1]);
                float2 v1 = make_float2(acc[i][j][2], acc[i][j][3]);
                if (round_out) {
                    v0.x = to_tf32(v0.x); v0.y = to_tf32(v0.y);
                    v1.x = to_tf32(v1.x); v1.y = to_tf32(v1.y);
                }
                *(float2*)&C[(size_t)r0 * N + col]       = v0;
                *(float2*)&C[(size_t)(r0 + 8) * N + col] = v1;
            }
        }
    }
}

// ---------------------------------------------------------------------------
// RMSNorm (in place)
// ---------------------------------------------------------------------------
__global__ void rmsnorm_kernel(float* __restrict__ x,
                               const float* __restrict__ scale, int D)
{
    __shared__ float red[32];
    float* p = x + (size_t)blockIdx.x * D;

    float ss = 0.f;
    for (int d = threadIdx.x; d < D; d += blockDim.x) {
        float v = p[d];
        ss += v * v;
    }
#pragma unroll
    for (int o = 16; o; o >>= 1) ss += __shfl_xor_sync(0xffffffffu, ss, o);
    if ((threadIdx.x & 31) == 0) red[threadIdx.x >> 5] = ss;
    __syncthreads();
    if (threadIdx.x < 32) {
        float v = (threadIdx.x < (blockDim.x >> 5)) ? red[threadIdx.x] : 0.f;
#pragma unroll
        for (int o = 16; o; o >>= 1) v += __shfl_xor_sync(0xffffffffu, v, o);
        if (threadIdx.x == 0) red[0] = v;
    }
    __syncthreads();
    float inv = rsqrtf(red[0] / (float)D + EPS);
    for (int d = threadIdx.x; d < D; d += blockDim.x)
        p[d] = p[d] * inv * scale[d];
}

// ---------------------------------------------------------------------------
// RoPE tables / application (rope outputs tf32-rounded: consumed only by mma)
// ---------------------------------------------------------------------------
__global__ void rope_table_kernel(float* __restrict__ ctab, float* __restrict__ stab)
{
    int idx = blockIdx.x * blockDim.x + threadIdx.x;
    if (idx >= S * (ROPE / 2)) return;
    int i = idx % (ROPE / 2);
    int s = idx / (ROPE / 2);
    float freq = (float)pow(10000.0, -((double)(2 * i)) / (double)ROPE);
    float ang  = (float)s * freq;
    double a   = (double)ang;
    ctab[idx] = (float)cos(a);
    stab[idx] = (float)sin(a);
}

__global__ void rope_q_kernel(float* __restrict__ q,
                              const float* __restrict__ ctab,
                              const float* __restrict__ stab)
{
    int idx = blockIdx.x * blockDim.x + threadIdx.x;
    if (idx >= T * NH * (ROPE / 2)) return;
    int i   = idx & 31;
    int rem = idx >> 5;
    int h   = rem & (NH - 1);
    int tok = rem >> 4;
    int s   = tok & (S - 1);
    float c  = ctab[s * 32 + i];
    float sn = stab[s * 32 + i];
    float* p = q + (size_t)tok * (NH * ROPE) + h * ROPE + 2 * i;
    float x1 = p[0], x2 = p[1];
    p[0] = to_tf32(x1 * c - x2 * sn);
    p[1] = to_tf32(x1 * sn + x2 * c);
}

__global__ void rope_k_kernel(float* __restrict__ k,
                              const float* __restrict__ ctab,
                              const float* __restrict__ stab)
{
    int idx = blockIdx.x * blockDim.x + threadIdx.x;
    if (idx >= T * (ROPE / 2)) return;
    int i   = idx & 31;
    int tok = idx >> 5;
    int s   = tok & (S - 1);
    float c  = ctab[s * 32 + i];
    float sn = stab[s * 32 + i];
    float* p = k + (size_t)tok * ROPE + 2 * i;
    float x1 = p[0], x2 = p[1];
    p[0] = to_tf32((x1 * c - x2 * sn) * 0.0625f);   // /NH folded in
    p[1] = to_tf32((x1 * sn + x2 * c) * 0.0625f);
}

// ---------------------------------------------------------------------------
// Flash attention: BQ=128, 512 threads. Skewed 3-barrier pipeline:
//   [STS V(t); QK(t)] barA [LDG V(t+1); STS Kf(t+1); LDG K(t+2); softmax(t)]
//   barB [PV(t)] barC
// Staging overlaps compute; one barrier fewer per iteration.
// ---------------------------------------------------------------------------
constexpr int BQ  = 128;
constexpr int BKT = 64;
constexpr int VSTR = 136;
constexpr int PSTR = 68;

struct AttnSmem {
    float Qf[8 * 24 * 32 * 4];
    float Kf[8 * 24 * 32 * 2];
    float V[BKT][VSTR];
    float P[BQ][PSTR];
    float alpha[BQ];
    float invl[BQ];
};

__global__ void __launch_bounds__(512)
attn_kernel(const float* __restrict__ qn, const float* __restrict__ qr,
            const float* __restrict__ kn, const float* __restrict__ kr,
            const float* __restrict__ v,  float* __restrict__ out)
{
    extern __shared__ char smraw[];
    AttnSmem& sm = *reinterpret_cast<AttnSmem*>(smraw);

    const int qt = (gridDim.x - 1) - blockIdx.x;   // heavy blocks first
    const int h  = blockIdx.y;
    const int b  = blockIdx.z;
    const int tid = threadIdx.x;
    const int lane = tid & 31;
    const int warp = tid >> 5;
    const int qid  = lane >> 2;
    const int rid  = lane & 3;
    const int qb = b * S + qt * BQ;

    const int mtile = warp & 7;
    const int ntb   = (warp >> 3) * 4;
    const int row0 = mtile * 16 + qid;
    const int nbv  = (warp >> 3) * 64;

    const int krn[4] = { tid >> 5, (tid + 512) >> 5, (tid + 1024) >> 5, (tid + 1536) >> 5 };
    const int kcn    = (tid & 31) * 4;
    const int krr[2] = { tid >> 4, (tid + 512) >> 4 };
    const int kcr    = (tid & 15) * 4;

    // ---- stage Q tile [128 x 192] into fragment layout ----
    for (int idx = tid; idx < BQ * 32; idx += 512) {
        int r = idx >> 5, dq = (idx & 31) * 4;
        st_afrag_raw<24>(sm.Qf, r, dq,
            *(const float4*)&qn[(size_t)(qb + r) * (NH * NOPE) + h * NOPE + dq]);
    }
    for (int idx = tid; idx < BQ * 16; idx += 512) {
        int r = idx >> 4, dq = (idx & 15) * 4;
        st_afrag_raw<24>(sm.Qf, r, 128 + dq,
            *(const float4*)&qr[(size_t)(qb + r) * (NH * ROPE) + h * ROPE + dq]);
    }

    const int srow = tid >> 2, squad = tid & 3;

    float m = -1e30f, l = 0.f;    // m in log2 domain
    float acc[8][4];
#pragma unroll
    for (int j = 0; j < 8; j++)
#pragma unroll
        for (int c = 0; c < 4; c++) acc[j][c] = 0.f;

    const int nkt = 2 * qt + 2;

    // ---- prologue: load tile 0 regs, stage Kf(0), then prefetch K(1) ----
    float4 kb[6], vb[4];
    {
        const int kbT = b * S;
#pragma unroll
        for (int i = 0; i < 4; i++)
            kb[i] = *(const float4*)&kn[(size_t)(kbT + krn[i]) * (NH * NOPE) + h * NOPE + kcn];
#pragma unroll
        for (int i = 0; i < 2; i++)
            kb[4 + i] = *(const float4*)&kr[(size_t)(kbT + krr[i]) * ROPE + kcr];
#pragma unroll
        for (int i = 0; i < 4; i++)
            vb[i] = *(const float4*)&v[(size_t)(kbT + krn[i]) * (NH * VD) + h * VD + kcn];
    }
#pragma unroll
    for (int i = 0; i < 4; i++) st_bfrag_raw<24>(sm.Kf, krn[i], kcn, kb[i]);
#pragma unroll
    for (int i = 0; i < 2; i++) st_bfrag_raw<24>(sm.Kf, krr[i], 128 + kcr, kb[4 + i]);
    __syncthreads();            // Qf + Kf(0) visible
    if (1 < nkt) {
        const int kbT = b * S + BKT;
#pragma unroll
        for (int i = 0; i < 4; i++)
            kb[i] = *(const float4*)&kn[(size_t)(kbT + krn[i]) * (NH * NOPE) + h * NOPE + kcn];
#pragma unroll
        for (int i = 0; i < 2; i++)
            kb[4 + i] = *(const float4*)&kr[(size_t)(kbT + krr[i]) * ROPE + kcr];
    }

    for (int kt = 0; kt < nkt; kt++) {
        // ---- stage V(kt) (buffer free: PV(kt-1) drained at barC) ----
#pragma unroll
        for (int i = 0; i < 4; i++) *(float4*)&sm.V[krn[i]][kcn] = vb[i];

        // ---- QK(kt) via tf32 mma (reads Qf, Kf(kt); never reads V) ----
        {
            float c[4][4];
#pragma unroll
            for (int j = 0; j < 4; j++)
#pragma unroll
                for (int cc = 0; cc < 4; cc++) c[j][cc] = 0.f;

#pragma unroll
            for (int ks = 0; ks < 24; ks++) {
                float4 a = *(const float4*)&sm.Qf[((mtile * 24 + ks) * 32 + lane) * 4];
#pragma unroll
                for (int j = 0; j < 4; j++) {
                    float2 bb = *(const float2*)&sm.Kf[(((ntb + j) * 24 + ks) * 32 + lane) * 2];
                    mma_tf32(c[j][0], c[j][1], c[j][2], c[j][3],
                             a.x, a.y, a.z, a.w, bb.x, bb.y);
                }
            }

            const bool diag = (kt >= 2 * qt);
            const int r0 = mtile * 16 + qid;
#pragma unroll
            for (int j = 0; j < 4; j++) {
                int col = (ntb + j) * 8 + rid * 2;
                int ki0 = kt * BKT + col;
                float s0 = c[j][0] * SM_SCALE2, s1 = c[j][1] * SM_SCALE2;
                float s2 = c[j][2] * SM_SCALE2, s3 = c[j][3] * SM_SCALE2;
                if (diag) {
                    int qi0 = qt * BQ + r0;
                    int qi1 = qi0 + 8;
                    if (ki0     > qi0) s0 = MASK2;
                    if (ki0 + 1 > qi0) s1 = MASK2;
                    if (ki0     > qi1) s2 = MASK2;
                    if (ki0 + 1 > qi1) s3 = MASK2;
                }
                *(float2*)&sm.P[r0][col]     = make_float2(s0, s1);
                *(float2*)&sm.P[r0 + 8][col] = make_float2(s2, s3);
            }
        }
        __syncthreads();   // barA: QK(kt) done; V(kt) stores visible

        // ---- prefetch V(kt+1) regs; stage Kf(kt+1); prefetch K(kt+2) ----
        if (kt + 1 < nkt) {
            const int vT = b * S + (kt + 1) * BKT;
#pragma unroll
            for (int i = 0; i < 4; i++)
                vb[i] = *(const float4*)&v[(size_t)(vT + krn[i]) * (NH * VD) + h * VD + kcn];
#pragma unroll
            for (int i = 0; i < 4; i++) st_bfrag_raw<24>(sm.Kf, krn[i], kcn, kb[i]);
#pragma unroll
            for (int i = 0; i < 2; i++) st_bfrag_raw<24>(sm.Kf, krr[i], 128 + kcr, kb[4 + i]);
            if (kt + 2 < nkt) {
                const int kT = b * S + (kt + 2) * BKT;
#pragma unroll
                for (int i = 0; i < 4; i++)
                    kb[i] = *(const float4*)&kn[(size_t)(kT + krn[i]) * (NH * NOPE) + h * NOPE + kcn];
#pragma unroll
                for (int i = 0; i < 2; i++)
                    kb[4 + i] = *(const float4*)&kr[(size_t)(kT + krr[i]) * ROPE + kcr];
            }
        }

        // ---- online softmax(kt): strided cols, exp2 domain ----
        {
            float sv[16];
            float tmax = -1e30f;
#pragma unroll
            for (int jj = 0; jj < 16; jj++) {
                sv[jj] = sm.P[srow][jj * 4 + squad];
                tmax = fmaxf(tmax, sv[jj]);
            }
            tmax = fmaxf(tmax, __shfl_xor_sync(0xffffffffu, tmax, 1));
            tmax = fmaxf(tmax, __shfl_xor_sync(0xffffffffu, tmax, 2));
            float mnew = fmaxf(m, tmax);
            float al   = exp2f(m - mnew);
            float ps = 0.f;
#pragma unroll
            for (int jj = 0; jj < 16; jj++) {
                float p = exp2f(sv[jj] - mnew);
                sm.P[srow][jj * 4 + squad] = to_tf32(p);
                ps += p;
            }
            ps += __shfl_xor_sync(0xffffffffu, ps, 1);
            ps += __shfl_xor_sync(0xffffffffu, ps, 2);
            l = l * al + ps;
            m = mnew;
            if (squad == 0) sm.alpha[srow] = al;
        }
        __syncthreads();   // barB: P ready; Kf(kt+1) visible

        // ---- PV(kt) via tf32 mma ----
        {
            const float al0 = sm.alpha[row0];
            const float al1 = sm.alpha[row0 + 8];
#pragma unroll
            for (int j = 0; j < 8; j++) {
                acc[j][0] *= al0; acc[j][1] *= al0;
                acc[j][2] *= al1; acc[j][3] *= al1;
            }
#pragma unroll
            for (int ks = 0; ks < 8; ks++) {
                const float a0 = sm.P[row0]    [ks * 8 + rid];
                const float a1 = sm.P[row0 + 8][ks * 8 + rid];
                const float a2 = sm.P[row0]    [ks * 8 + rid + 4];
                const float a3 = sm.P[row0 + 8][ks * 8 + rid + 4];
#pragma unroll
                for (int j = 0; j < 8; j++) {
                    const float b0 = sm.V[ks * 8 + rid]    [nbv + j * 8 + qid];
                    const float b1 = sm.V[ks * 8 + rid + 4][nbv + j * 8 + qid];
                    mma_tf32(acc[j][0], acc[j][1], acc[j][2], acc[j][3],
                             a0, a1, a2, a3, b0, b1);
                }
            }
        }
        __syncthreads();   // barC: PV(kt) drained; V/P free for next iter
    }

    if (squad == 0) sm.invl[srow] = 1.f / l;
    __syncthreads();

    // ---- epilogue ----
    {
        const float il0 = sm.invl[row0];
        const float il1 = sm.invl[row0 + 8];
        const int tok0 = qb + row0;
        const int tok1 = tok0 + 8;
#pragma unroll
        for (int j = 0; j < 8; j++) {
            const int col = nbv + j * 8 + rid * 2;
            *(float2*)&out[(size_t)tok0 * (NH * VD) + h * VD + col] =
                make_float2(acc[j][0] * il0, acc[j][1] * il0);
            *(float2*)&out[(size_t)tok1 * (NH * VD) + h * VD + col] =
                make_float2(acc[j][2] * il1, acc[j][3] * il1);
        }
    }
}

// ---------------------------------------------------------------------------
// Launch (Q path and KV path forked onto concurrent streams inside capture)
// ---------------------------------------------------------------------------
static void launch_gemm_s(cudaStream_t s, const float* A, const float* B, float* C,
                          int M, int N, int K, int round_out = 0)
{
    dim3 grid((N + 127) / 128, (M + 127) / 128);
    tf32_gemm_kernel<<<grid, 256, 0, s>>>(A, B, C, M, N, K, round_out);
}

extern "C" void kernel_launch(void* const* d_in, const int* in_sizes, int n_in,
                              void* d_out, int out_size)
{
    const float* x         = (const float*)d_in[0];
    const float* W_cq      = (const float*)d_in[1];
    const float* q_scale   = (const float*)d_in[2];
    const float* W_dq_nope = (const float*)d_in[3];
    const float* W_dq_rope = (const float*)d_in[4];
    const float* W_ckv     = (const float*)d_in[5];
    const float* kv_scale  = (const float*)d_in[6];
    const float* W_dk_nope = (const float*)d_in[7];
    const float* W_dv      = (const float*)d_in[8];
    const float* W_krope   = (const float*)d_in[9];
    const float* W_o       = (const float*)d_in[10];
    float* out = (float*)d_out;

    float *cq, *qn, *qr, *ckv, *kn, *vv, *kr, *att, *ctab, *stab;
    cudaGetSymbolAddress((void**)&cq,  g_cq);
    cudaGetSymbolAddress((void**)&qn,  g_qnope);
    cudaGetSymbolAddress((void**)&qr,  g_qrope);
    cudaGetSymbolAddress((void**)&ckv, g_ckv);
    cudaGetSymbolAddress((void**)&kn,  g_knope);
    cudaGetSymbolAddress((void**)&vv,  g_v);
    cudaGetSymbolAddress((void**)&kr,  g_krope);
    cudaGetSymbolAddress((void**)&att, g_attn);
    cudaGetSymbolAddress((void**)&ctab, g_ctab);
    cudaGetSymbolAddress((void**)&stab, g_stab);

    // Fork/join machinery (host-only cost; harness times graph replays).
    cudaStream_t s0 = 0;
    cudaStream_t skv;
    cudaEvent_t ev_fork, ev_kv;
    cudaStreamCreateWithFlags(&skv, cudaStreamNonBlocking);
    cudaEventCreateWithFlags(&ev_fork, cudaEventDisableTiming);
    cudaEventCreateWithFlags(&ev_kv,  cudaEventDisableTiming);

    // RoPE tables (needed by both paths)
    rope_table_kernel<<<(S * 32 + 255) / 256, 256, 0, s0>>>(ctab, stab);

    // ---- fork: KV path on skv ----
    cudaEventRecord(ev_fork, s0);
    cudaStreamWaitEvent(skv, ev_fork, 0);

    // KV path (skv)
    launch_gemm_s(skv, x, W_krope, kr, T, ROPE, H);
    rope_k_kernel<<<(T * 32 + 255) / 256, 256, 0, skv>>>(kr, ctab, stab);
    launch_gemm_s(skv, x, W_ckv, ckv, T, KVR, H);
    rmsnorm_kernel<<<T, 256, 0, skv>>>(ckv, kv_scale, KVR);
    launch_gemm_s(skv, ckv, W_dk_nope, kn, T, NH * NOPE, KVR, 1); // tf32 out
    launch_gemm_s(skv, ckv, W_dv, vv, T, NH * VD, KVR, 1);        // tf32 out
    cudaEventRecord(ev_kv, skv);

    // Q path (s0)
    launch_gemm_s(s0, x, W_cq, cq, T, QR, H);
    rmsnorm_kernel<<<T, 256, 0, s0>>>(cq, q_scale, QR);
    launch_gemm_s(s0, cq, W_dq_nope, qn, T, NH * NOPE, QR, 1);    // tf32 out
    launch_gemm_s(s0, cq, W_dq_rope, qr, T, NH * ROPE, QR);
    rope_q_kernel<<<(T * NH * 32 + 255) / 256, 256, 0, s0>>>(qr, ctab, stab);

    // ---- join ----
    cudaStreamWaitEvent(s0, ev_kv, 0);

    // Attention
    cudaFuncSetAttribute((const void*)attn_kernel,
                         cudaFuncAttributeMaxDynamicSharedMemorySize,
                         (int)sizeof(AttnSmem));
    attn_kernel<<<dim3(S / BQ, NH, BB), 512, sizeof(AttnSmem), s0>>>(qn, qr, kn, kr, vv, att);

    // Output projection
    launch_gemm_s(s0, att, W_o, out, T, H, NH * VD);
}

// round 13
// speedup vs baseline: 1.2898x; 1.0116x over previous
#include <cuda_runtime.h>
#include <math.h>
#include <stdint.h>

// ---------------------------------------------------------------------------
// Problem constants
// ---------------------------------------------------------------------------
constexpr int H    = 2048;
constexpr int NH   = 16;
constexpr int NOPE = 128;
constexpr int ROPE = 64;
constexpr int VD   = 128;
constexpr int QR   = 1024;
constexpr int KVR  = 512;
constexpr int BB   = 2;       // batch
constexpr int S    = 2048;    // seq len
constexpr int T    = BB * S;  // 4096 tokens
constexpr float EPS = 1e-6f;
constexpr float SM_SCALE2 = 0.10412105626079532f;         // (1/sqrt(192)) * log2(e)
constexpr float MASK2 = -1.4426950408889634e9f;           // -1e9 * log2(e)

// ---------------------------------------------------------------------------
// Device scratch (allocation-free rule: __device__ globals)
// ---------------------------------------------------------------------------
__device__ float g_cq   [T * QR];
__device__ float g_qnope[T * NH * NOPE];
__device__ float g_qrope[T * NH * ROPE];
__device__ float g_ckv  [T * KVR];
__device__ float g_knope[T * NH * NOPE];
__device__ float g_v    [T * NH * VD];
__device__ float g_krope[T * ROPE];
__device__ float g_attn [T * NH * VD];
__device__ float g_ctab [S * (ROPE / 2)];
__device__ float g_stab [S * (ROPE / 2)];

// ---------------------------------------------------------------------------
// tf32 helpers
// ---------------------------------------------------------------------------
__device__ __forceinline__ float to_tf32(float x) {
    uint32_t u;
    asm("cvt.rna.tf32.f32 %0, %1;" : "=r"(u) : "f"(x));
    return __uint_as_float(u);
}
__device__ __forceinline__ float4 to_tf32x4(float4 v) {
    return make_float4(to_tf32(v.x), to_tf32(v.y), to_tf32(v.z), to_tf32(v.w));
}

__device__ __forceinline__ void mma_tf32(float& c0, float& c1, float& c2, float& c3,
                                         float a0, float a1, float a2, float a3,
                                         float b0, float b1)
{
    uint32_t ua0 = __float_as_uint(a0), ua1 = __float_as_uint(a1);
    uint32_t ua2 = __float_as_uint(a2), ua3 = __float_as_uint(a3);
    uint32_t ub0 = __float_as_uint(b0), ub1 = __float_as_uint(b1);
    asm volatile(
        "mma.sync.aligned.m16n8k8.row.col.f32.tf32.tf32.f32 "
        "{%0,%1,%2,%3}, {%4,%5,%6,%7}, {%8,%9}, {%0,%1,%2,%3};\n"
        : "+f"(c0), "+f"(c1), "+f"(c2), "+f"(c3)
        : "r"(ua0), "r"(ua1), "r"(ua2), "r"(ua3), "r"(ub0), "r"(ub1));
}

// Fragment-order smem stores (values already tf32-rounded by producers).
template<int KSTEPS>
__device__ __forceinline__ void st_afrag_raw(float* F, int m, int k, float4 v) {
    float* dst = F + (((m >> 4) * KSTEPS + (k >> 3)) * 32 + (m & 7) * 4 + (k & 3)) * 4
                   + ((m >> 3) & 1) + (((k >> 2) & 1) << 1);
    dst[0]  = v.x;
    dst[4]  = v.y;
    dst[8]  = v.z;
    dst[12] = v.w;
}
template<int KSTEPS>
__device__ __forceinline__ void st_bfrag_raw(float* F, int r, int d, float4 v) {
    float* dst = F + (((r >> 3) * KSTEPS + (d >> 3)) * 32 + (r & 7) * 4 + (d & 3)) * 2
                   + ((d >> 2) & 1);
    dst[0] = v.x;
    dst[2] = v.y;
    dst[4] = v.z;
    dst[6] = v.w;
}

// ---------------------------------------------------------------------------
// tf32 tensor-core GEMM (proven): C[M,N] = A[M,K] @ B[K,N].
// round_out != 0 -> store tf32-rounded results (for attention inputs).
// ---------------------------------------------------------------------------
constexpr int AS_STRIDE = 20;
constexpr int BS_STRIDE = 136;

__global__ void __launch_bounds__(256)
tf32_gemm_kernel(const float* __restrict__ A, const float* __restrict__ B,
                 float* __restrict__ C, int M, int N, int K, int round_out)
{
    __shared__ float As[2][128][AS_STRIDE];
    __shared__ float Bs[2][16][BS_STRIDE];

    const int tid  = threadIdx.x;
    const int lane = tid & 31;
    const int warp = tid >> 5;
    const int qid  = lane >> 2;
    const int rid  = lane & 3;
    const int wr   = (warp >> 2) * 64;
    const int wc   = (warp & 3) * 32;

    const int rowBase = blockIdx.y * 128;
    const int colBase = blockIdx.x * 128;

    const int ar0 = tid >> 2;
    const int ar1 = ar0 + 64;
    const int ac  = (tid & 3) * 4;
    const int bk0 = tid >> 5;
    const int bk1 = bk0 + 8;
    const int bn  = (tid & 31) * 4;
    const int gn  = colBase + bn;
    const bool bok = (gn < N);

    float acc[4][4][4];
#pragma unroll
    for (int i = 0; i < 4; i++)
#pragma unroll
        for (int j = 0; j < 4; j++)
#pragma unroll
            for (int c = 0; c < 4; c++) acc[i][j][c] = 0.f;

    const int nt = K / 16;
    float4 ra0, ra1, rb0, rb1;

    ra0 = *(const float4*)&A[(size_t)(rowBase + ar0) * K + ac];
    ra1 = *(const float4*)&A[(size_t)(rowBase + ar1) * K + ac];
    rb0 = bok ? *(const float4*)&B[(size_t)bk0 * N + gn] : make_float4(0,0,0,0);
    rb1 = bok ? *(const float4*)&B[(size_t)bk1 * N + gn] : make_float4(0,0,0,0);
    *(float4*)&As[0][ar0][ac] = to_tf32x4(ra0);
    *(float4*)&As[0][ar1][ac] = to_tf32x4(ra1);
    *(float4*)&Bs[0][bk0][bn] = to_tf32x4(rb0);
    *(float4*)&Bs[0][bk1][bn] = to_tf32x4(rb1);
    __syncthreads();

    for (int t = 0; t < nt; t++) {
        const int buf = t & 1;

        if (t + 1 < nt) {
            const int k0 = (t + 1) * 16;
            ra0 = *(const float4*)&A[(size_t)(rowBase + ar0) * K + k0 + ac];
            ra1 = *(const float4*)&A[(size_t)(rowBase + ar1) * K + k0 + ac];
            rb0 = bok ? *(const float4*)&B[(size_t)(k0 + bk0) * N + gn] : make_float4(0,0,0,0);
            rb1 = bok ? *(const float4*)&B[(size_t)(k0 + bk1) * N + gn] : make_float4(0,0,0,0);
        }

#pragma unroll
        for (int ks = 0; ks < 16; ks += 8) {
            float a[4][4], b[4][2];
#pragma unroll
            for (int i = 0; i < 4; i++) {
                const float* p0 = &As[buf][wr + i * 16 + qid][ks + rid];
                const float* p1 = &As[buf][wr + i * 16 + qid + 8][ks + rid];
                a[i][0] = p0[0];
                a[i][1] = p1[0];
                a[i][2] = p0[4];
                a[i][3] = p1[4];
            }
#pragma unroll
            for (int j = 0; j < 4; j++) {
                b[j][0] = Bs[buf][ks + rid][wc + j * 8 + qid];
                b[j][1] = Bs[buf][ks + rid + 4][wc + j * 8 + qid];
            }
#pragma unroll
            for (int i = 0; i < 4; i++)
#pragma unroll
                for (int j = 0; j < 4; j++)
                    mma_tf32(acc[i][j][0], acc[i][j][1], acc[i][j][2], acc[i][j][3],
                             a[i][0], a[i][1], a[i][2], a[i][3],
                             b[j][0], b[j][1]);
        }

        if (t + 1 < nt) {
            const int nb = (t + 1) & 1;
            *(float4*)&As[nb][ar0][ac] = to_tf32x4(ra0);
            *(float4*)&As[nb][ar1][ac] = to_tf32x4(ra1);
            *(float4*)&Bs[nb][bk0][bn] = to_tf32x4(rb0);
            *(float4*)&Bs[nb][bk1][bn] = to_tf32x4(rb1);
        }
        __syncthreads();
    }

#pragma unroll
    for (int i = 0; i < 4; i++) {
        const int r0 = rowBase + wr + i * 16 + qid;
#pragma unroll
        for (int j = 0; j < 4; j++) {
            const int col = colBase + wc + j * 8 + rid * 2;
            if (col < N) {
                float2 v0 = make_float2(acc[i][j][0], acc[i][j][1]);
                float2 v1 = make_float2(acc[i][j][2], acc[i][j][3]);
                if (round_out) {
                    v0.x = to_tf32(v0.x); v0.y = to_tf32(v0.y);
                    v1.x = to_tf32(v1.x); v1.y = to_tf32(v1.y);
                }
                *(float2*)&C[(size_t)r0 * N + col]       = v0;
                *(float2*)&C[(size_t)(r0 + 8) * N + col] = v1;
            }
        }
    }
}

// ---------------------------------------------------------------------------
// RMSNorm (in place)
// ---------------------------------------------------------------------------
__global__ void rmsnorm_kernel(float* __restrict__ x,
                               const float* __restrict__ scale, int D)
{
    __shared__ float red[32];
    float* p = x + (size_t)blockIdx.x * D;

    float ss = 0.f;
    for (int d = threadIdx.x; d < D; d += blockDim.x) {
        float v = p[d];
        ss += v * v;
    }
#pragma unroll
    for (int o = 16; o; o >>= 1) ss += __shfl_xor_sync(0xffffffffu, ss, o);
    if ((threadIdx.x & 31) == 0) red[threadIdx.x >> 5] = ss;
    __syncthreads();
    if (threadIdx.x < 32) {
        float v = (threadIdx.x < (blockDim.x >> 5)) ? red[threadIdx.x] : 0.f;
#pragma unroll
        for (int o = 16; o; o >>= 1) v += __shfl_xor_sync(0xffffffffu, v, o);
        if (threadIdx.x == 0) red[0] = v;
    }
    __syncthreads();
    float inv = rsqrtf(red[0] / (float)D + EPS);
    for (int d = threadIdx.x; d < D; d += blockDim.x)
        p[d] = p[d] * inv * scale[d];
}

// ---------------------------------------------------------------------------
// RoPE tables / application (rope outputs tf32-rounded: consumed only by mma)
// ---------------------------------------------------------------------------
__global__ void rope_table_kernel(float* __restrict__ ctab, float* __restrict__ stab)
{
    int idx = blockIdx.x * blockDim.x + threadIdx.x;
    if (idx >= S * (ROPE / 2)) return;
    int i = idx % (ROPE / 2);
    int s = idx / (ROPE / 2);
    float freq = (float)pow(10000.0, -((double)(2 * i)) / (double)ROPE);
    float ang  = (float)s * freq;
    double a   = (double)ang;
    ctab[idx] = (float)cos(a);
    stab[idx] = (float)sin(a);
}

__global__ void rope_q_kernel(float* __restrict__ q,
                              const float* __restrict__ ctab,
                              const float* __restrict__ stab)
{
    int idx = blockIdx.x * blockDim.x + threadIdx.x;
    if (idx >= T * NH * (ROPE / 2)) return;
    int i   = idx & 31;
    int rem = idx >> 5;
    int h   = rem & (NH - 1);
    int tok = rem >> 4;
    int s   = tok & (S - 1);
    float c  = ctab[s * 32 + i];
    float sn = stab[s * 32 + i];
    float* p = q + (size_t)tok * (NH * ROPE) + h * ROPE + 2 * i;
    float x1 = p[0], x2 = p[1];
    p[0] = to_tf32(x1 * c - x2 * sn);
    p[1] = to_tf32(x1 * sn + x2 * c);
}

__global__ void rope_k_kernel(float* __restrict__ k,
                              const float* __restrict__ ctab,
                              const float* __restrict__ stab)
{
    int idx = blockIdx.x * blockDim.x + threadIdx.x;
    if (idx >= T * (ROPE / 2)) return;
    int i   = idx & 31;
    int tok = idx >> 5;
    int s   = tok & (S - 1);
    float c  = ctab[s * 32 + i];
    float sn = stab[s * 32 + i];
    float* p = k + (size_t)tok * ROPE + 2 * i;
    float x1 = p[0], x2 = p[1];
    p[0] = to_tf32((x1 * c - x2 * sn) * 0.0625f);   // /NH folded in
    p[1] = to_tf32((x1 * sn + x2 * c) * 0.0625f);
}

// ---------------------------------------------------------------------------
// Flash attention: BQ=128, 512 threads, IN-REGISTER online softmax.
// Scores never round-trip through smem: QK mma leaves them in registers;
// row max/sum combined across the two column-half warps via tiny smem
// exchanges; exp2 from registers; only final tf32 P is stored for PV mma.
// ---------------------------------------------------------------------------
constexpr int BQ  = 128;
constexpr int BKT = 64;
constexpr int VSTR = 136;
constexpr int PSTR = 68;

struct AttnSmem {
    float Qf[8 * 24 * 32 * 4];
    float Kf[8 * 24 * 32 * 2];
    float V[BKT][VSTR];
    float P[BQ][PSTR];
    float rowmax[2][BQ];
    float rowsum[2][BQ];
};

__global__ void __launch_bounds__(512)
attn_kernel(const float* __restrict__ qn, const float* __restrict__ qr,
            const float* __restrict__ kn, const float* __restrict__ kr,
            const float* __restrict__ v,  float* __restrict__ out)
{
    extern __shared__ char smraw[];
    AttnSmem& sm = *reinterpret_cast<AttnSmem*>(smraw);

    const int qt = (gridDim.x - 1) - blockIdx.x;   // heavy blocks first
    const int h  = blockIdx.y;
    const int b  = blockIdx.z;
    const int tid = threadIdx.x;
    const int lane = tid & 31;
    const int warp = tid >> 5;
    const int qid  = lane >> 2;
    const int rid  = lane & 3;
    const int qb = b * S + qt * BQ;

    const int mtile = warp & 7;
    const int half  = warp >> 3;         // column half (0 or 1)
    const int ntb   = half * 4;
    const int row0 = mtile * 16 + qid;
    const int nbv  = half * 64;

    const int krn[4] = { tid >> 5, (tid + 512) >> 5, (tid + 1024) >> 5, (tid + 1536) >> 5 };
    const int kcn    = (tid & 31) * 4;
    const int krr[2] = { tid >> 4, (tid + 512) >> 4 };
    const int kcr    = (tid & 15) * 4;

    // ---- stage Q tile [128 x 192] into fragment layout ----
    for (int idx = tid; idx < BQ * 32; idx += 512) {
        int r = idx >> 5, dq = (idx & 31) * 4;
        st_afrag_raw<24>(sm.Qf, r, dq,
            *(const float4*)&qn[(size_t)(qb + r) * (NH * NOPE) + h * NOPE + dq]);
    }
    for (int idx = tid; idx < BQ * 16; idx += 512) {
        int r = idx >> 4, dq = (idx & 15) * 4;
        st_afrag_raw<24>(sm.Qf, r, 128 + dq,
            *(const float4*)&qr[(size_t)(qb + r) * (NH * ROPE) + h * ROPE + dq]);
    }

    // per-thread online-softmax state for its two rows (log2 domain)
    float m0 = -1e30f, m1 = -1e30f, l0 = 0.f, l1 = 0.f;
    float acc[8][4];
#pragma unroll
    for (int j = 0; j < 8; j++)
#pragma unroll
        for (int c = 0; c < 4; c++) acc[j][c] = 0.f;

    const int nkt = 2 * qt + 2;

    // ---- prologue: load tile 0 regs, stage Kf(0), then prefetch K(1) ----
    float4 kb[6], vb[4];
    {
        const int kbT = b * S;
#pragma unroll
        for (int i = 0; i < 4; i++)
            kb[i] = *(const float4*)&kn[(size_t)(kbT + krn[i]) * (NH * NOPE) + h * NOPE + kcn];
#pragma unroll
        for (int i = 0; i < 2; i++)
            kb[4 + i] = *(const float4*)&kr[(size_t)(kbT + krr[i]) * ROPE + kcr];
#pragma unroll
        for (int i = 0; i < 4; i++)
            vb[i] = *(const float4*)&v[(size_t)(kbT + krn[i]) * (NH * VD) + h * VD + kcn];
    }
#pragma unroll
    for (int i = 0; i < 4; i++) st_bfrag_raw<24>(sm.Kf, krn[i], kcn, kb[i]);
#pragma unroll
    for (int i = 0; i < 2; i++) st_bfrag_raw<24>(sm.Kf, krr[i], 128 + kcr, kb[4 + i]);
    __syncthreads();            // Qf + Kf(0) visible
    if (1 < nkt) {
        const int kbT = b * S + BKT;
#pragma unroll
        for (int i = 0; i < 4; i++)
            kb[i] = *(const float4*)&kn[(size_t)(kbT + krn[i]) * (NH * NOPE) + h * NOPE + kcn];
#pragma unroll
        for (int i = 0; i < 2; i++)
            kb[4 + i] = *(const float4*)&kr[(size_t)(kbT + krr[i]) * ROPE + kcr];
    }

    for (int kt = 0; kt < nkt; kt++) {
        // ---- stage V(kt) (buffer free since barC of prev iter) ----
#pragma unroll
        for (int i = 0; i < 4; i++) *(float4*)&sm.V[krn[i]][kcn] = vb[i];

        // ---- QK(kt) via tf32 mma -> scores stay in registers ----
        float c[4][4];
#pragma unroll
        for (int j = 0; j < 4; j++)
#pragma unroll
            for (int cc = 0; cc < 4; cc++) c[j][cc] = 0.f;

#pragma unroll
        for (int ks = 0; ks < 24; ks++) {
            float4 a = *(const float4*)&sm.Qf[((mtile * 24 + ks) * 32 + lane) * 4];
#pragma unroll
            for (int j = 0; j < 4; j++) {
                float2 bb = *(const float2*)&sm.Kf[(((ntb + j) * 24 + ks) * 32 + lane) * 2];
                mma_tf32(c[j][0], c[j][1], c[j][2], c[j][3],
                         a.x, a.y, a.z, a.w, bb.x, bb.y);
            }
        }

        // scale + mask in registers
        {
            const bool diag = (kt >= 2 * qt);
#pragma unroll
            for (int j = 0; j < 4; j++) {
                int col = (ntb + j) * 8 + rid * 2;
                int ki0 = kt * BKT + col;
                c[j][0] *= SM_SCALE2; c[j][1] *= SM_SCALE2;
                c[j][2] *= SM_SCALE2; c[j][3] *= SM_SCALE2;
                if (diag) {
                    int qi0 = qt * BQ + row0;
                    int qi1 = qi0 + 8;
                    if (ki0     > qi0) c[j][0] = MASK2;
                    if (ki0 + 1 > qi0) c[j][1] = MASK2;
                    if (ki0     > qi1) c[j][2] = MASK2;
                    if (ki0 + 1 > qi1) c[j][3] = MASK2;
                }
            }
        }

        // per-row max over this warp's 32 columns (local 8 + shfl over rid)
        {
            float mx0 = fmaxf(fmaxf(c[0][0], c[0][1]), fmaxf(c[1][0], c[1][1]));
            mx0 = fmaxf(mx0, fmaxf(fmaxf(c[2][0], c[2][1]), fmaxf(c[3][0], c[3][1])));
            float mx1 = fmaxf(fmaxf(c[0][2], c[0][3]), fmaxf(c[1][2], c[1][3]));
            mx1 = fmaxf(mx1, fmaxf(fmaxf(c[2][2], c[2][3]), fmaxf(c[3][2], c[3][3])));
            mx0 = fmaxf(mx0, __shfl_xor_sync(0xffffffffu, mx0, 1));
            mx0 = fmaxf(mx0, __shfl_xor_sync(0xffffffffu, mx0, 2));
            mx1 = fmaxf(mx1, __shfl_xor_sync(0xffffffffu, mx1, 1));
            mx1 = fmaxf(mx1, __shfl_xor_sync(0xffffffffu, mx1, 2));
            if (rid == 0) {
                sm.rowmax[half][row0]     = mx0;
                sm.rowmax[half][row0 + 8] = mx1;
            }
        }
        __syncthreads();   // barA: rowmax halves + V(kt) stores visible

        // ---- combine max, exp from registers, write tf32 P, partial sums ----
        float al0, al1;
        {
            float f0 = fmaxf(sm.rowmax[0][row0],     sm.rowmax[1][row0]);
            float f1 = fmaxf(sm.rowmax[0][row0 + 8], sm.rowmax[1][row0 + 8]);
            float mn0 = fmaxf(m0, f0);
            float mn1 = fmaxf(m1, f1);
            al0 = exp2f(m0 - mn0);
            al1 = exp2f(m1 - mn1);
            m0 = mn0; m1 = mn1;

            float ps0 = 0.f, ps1 = 0.f;
#pragma unroll
            for (int j = 0; j < 4; j++) {
                float e0 = exp2f(c[j][0] - mn0);
                float e1 = exp2f(c[j][1] - mn0);
                float e2 = exp2f(c[j][2] - mn1);
                float e3 = exp2f(c[j][3] - mn1);
                ps0 += e0 + e1;
                ps1 += e2 + e3;
                int col = (ntb + j) * 8 + rid * 2;
                *(float2*)&sm.P[row0][col]     = make_float2(to_tf32(e0), to_tf32(e1));
                *(float2*)&sm.P[row0 + 8][col] = make_float2(to_tf32(e2), to_tf32(e3));
            }
            ps0 += __shfl_xor_sync(0xffffffffu, ps0, 1);
            ps0 += __shfl_xor_sync(0xffffffffu, ps0, 2);
            ps1 += __shfl_xor_sync(0xffffffffu, ps1, 1);
            ps1 += __shfl_xor_sync(0xffffffffu, ps1, 2);
            if (rid == 0) {
                sm.rowsum[half][row0]     = ps0;
                sm.rowsum[half][row0 + 8] = ps1;
            }
        }

        // ---- stage Kf(kt+1); prefetch V(kt+1), K(kt+2) regs ----
        if (kt + 1 < nkt) {
            const int vT = b * S + (kt + 1) * BKT;
#pragma unroll
            for (int i = 0; i < 4; i++)
                vb[i] = *(const float4*)&v[(size_t)(vT + krn[i]) * (NH * VD) + h * VD + kcn];
#pragma unroll
            for (int i = 0; i < 4; i++) st_bfrag_raw<24>(sm.Kf, krn[i], kcn, kb[i]);
#pragma unroll
            for (int i = 0; i < 2; i++) st_bfrag_raw<24>(sm.Kf, krr[i], 128 + kcr, kb[4 + i]);
            if (kt + 2 < nkt) {
                const int kT = b * S + (kt + 2) * BKT;
#pragma unroll
                for (int i = 0; i < 4; i++)
                    kb[i] = *(const float4*)&kn[(size_t)(kT + krn[i]) * (NH * NOPE) + h * NOPE + kcn];
#pragma unroll
                for (int i = 0; i < 2; i++)
                    kb[4 + i] = *(const float4*)&kr[(size_t)(kT + krr[i]) * ROPE + kcr];
            }
        }
        __syncthreads();   // barB: P + rowsum + Kf(kt+1) visible

        // ---- l update + PV(kt) via tf32 mma ----
        {
            l0 = l0 * al0 + (sm.rowsum[0][row0]     + sm.rowsum[1][row0]);
            l1 = l1 * al1 + (sm.rowsum[0][row0 + 8] + sm.rowsum[1][row0 + 8]);
#pragma unroll
            for (int j = 0; j < 8; j++) {
                acc[j][0] *= al0; acc[j][1] *= al0;
                acc[j][2] *= al1; acc[j][3] *= al1;
            }
#pragma unroll
            for (int ks = 0; ks < 8; ks++) {
                const float a0 = sm.P[row0]    [ks * 8 + rid];
                const float a1 = sm.P[row0 + 8][ks * 8 + rid];
                const float a2 = sm.P[row0]    [ks * 8 + rid + 4];
                const float a3 = sm.P[row0 + 8][ks * 8 + rid + 4];
#pragma unroll
                for (int j = 0; j < 8; j++) {
                    const float b0 = sm.V[ks * 8 + rid]    [nbv + j * 8 + qid];
                    const float b1 = sm.V[ks * 8 + rid + 4][nbv + j * 8 + qid];
                    mma_tf32(acc[j][0], acc[j][1], acc[j][2], acc[j][3],
                             a0, a1, a2, a3, b0, b1);
                }
            }
        }
        __syncthreads();   // barC: PV(kt) drained; V/P/rowmax free
    }

    // ---- epilogue: scale by 1/l (register state), write out ----
    {
        const float il0 = 1.f / l0;
        const float il1 = 1.f / l1;
        const int tok0 = qb + row0;
        const int tok1 = tok0 + 8;
#pragma unroll
        for (int j = 0; j < 8; j++) {
            const int col = nbv + j * 8 + rid * 2;
            *(float2*)&out[(size_t)tok0 * (NH * VD) + h * VD + col] =
                make_float2(acc[j][0] * il0, acc[j][1] * il0);
            *(float2*)&out[(size_t)tok1 * (NH * VD) + h * VD + col] =
                make_float2(acc[j][2] * il1, acc[j][3] * il1);
        }
    }
}

// ---------------------------------------------------------------------------
// Launch (Q path and KV path forked onto concurrent streams inside capture)
// ---------------------------------------------------------------------------
static void launch_gemm_s(cudaStream_t s, const float* A, const float* B, float* C,
                          int M, int N, int K, int round_out = 0)
{
    dim3 grid((N + 127) / 128, (M + 127) / 128);
    tf32_gemm_kernel<<<grid, 256, 0, s>>>(A, B, C, M, N, K, round_out);
}

extern "C" void kernel_launch(void* const* d_in, const int* in_sizes, int n_in,
                              void* d_out, int out_size)
{
    const float* x         = (const float*)d_in[0];
    const float* W_cq      = (const float*)d_in[1];
    const float* q_scale   = (const float*)d_in[2];
    const float* W_dq_nope = (const float*)d_in[3];
    const float* W_dq_rope = (const float*)d_in[4];
    const float* W_ckv     = (const float*)d_in[5];
    const float* kv_scale  = (const float*)d_in[6];
    const float* W_dk_nope = (const float*)d_in[7];
    const float* W_dv      = (const float*)d_in[8];
    const float* W_krope   = (const float*)d_in[9];
    const float* W_o       = (const float*)d_in[10];
    float* out = (float*)d_out;

    float *cq, *qn, *qr, *ckv, *kn, *vv, *kr, *att, *ctab, *stab;
    cudaGetSymbolAddress((void**)&cq,  g_cq);
    cudaGetSymbolAddress((void**)&qn,  g_qnope);
    cudaGetSymbolAddress((void**)&qr,  g_qrope);
    cudaGetSymbolAddress((void**)&ckv, g_ckv);
    cudaGetSymbolAddress((void**)&kn,  g_knope);
    cudaGetSymbolAddress((void**)&vv,  g_v);
    cudaGetSymbolAddress((void**)&kr,  g_krope);
    cudaGetSymbolAddress((void**)&att, g_attn);
    cudaGetSymbolAddress((void**)&ctab, g_ctab);
    cudaGetSymbolAddress((void**)&stab, g_stab);

    // Fork/join machinery (host-only cost; harness times graph replays).
    cudaStream_t s0 = 0;
    cudaStream_t skv;
    cudaEvent_t ev_fork, ev_kv;
    cudaStreamCreateWithFlags(&skv, cudaStreamNonBlocking);
    cudaEventCreateWithFlags(&ev_fork, cudaEventDisableTiming);
    cudaEventCreateWithFlags(&ev_kv,  cudaEventDisableTiming);

    // RoPE tables (needed by both paths)
    rope_table_kernel<<<(S * 32 + 255) / 256, 256, 0, s0>>>(ctab, stab);

    // ---- fork: KV path on skv ----
    cudaEventRecord(ev_fork, s0);
    cudaStreamWaitEvent(skv, ev_fork, 0);

    // KV path (skv)
    launch_gemm_s(skv, x, W_krope, kr, T, ROPE, H);
    rope_k_kernel<<<(T * 32 + 255) / 256, 256, 0, skv>>>(kr, ctab, stab);
    launch_gemm_s(skv, x, W_ckv, ckv, T, KVR, H);
    rmsnorm_kernel<<<T, 256, 0, skv>>>(ckv, kv_scale, KVR);
    launch_gemm_s(skv, ckv, W_dk_nope, kn, T, NH * NOPE, KVR, 1); // tf32 out
    launch_gemm_s(skv, ckv, W_dv, vv, T, NH * VD, KVR, 1);        // tf32 out
    cudaEventRecord(ev_kv, skv);

    // Q path (s0)
    launch_gemm_s(s0, x, W_cq, cq, T, QR, H);
    rmsnorm_kernel<<<T, 256, 0, s0>>>(cq, q_scale, QR);
    launch_gemm_s(s0, cq, W_dq_nope, qn, T, NH * NOPE, QR, 1);    // tf32 out
    launch_gemm_s(s0, cq, W_dq_rope, qr, T, NH * ROPE, QR);
    rope_q_kernel<<<(T * NH * 32 + 255) / 256, 256, 0, s0>>>(qr, ctab, stab);

    // ---- join ----
    cudaStreamWaitEvent(s0, ev_kv, 0);

    // Attention
    cudaFuncSetAttribute((const void*)attn_kernel,
                         cudaFuncAttributeMaxDynamicSharedMemorySize,
                         (int)sizeof(AttnSmem));
    attn_kernel<<<dim3(S / BQ, NH, BB), 512, sizeof(AttnSmem), s0>>>(qn, qr, kn, kr, vv, att);

    // Output projection
    launch_gemm_s(s0, att, W_o, out, T, H, NH * VD);
}

// round 14
// speedup vs baseline: 1.5746x; 1.2208x over previous
#include <cuda_runtime.h>
#include <cuda_fp16.h>
#include <math.h>
#include <stdint.h>

// ---------------------------------------------------------------------------
// Problem constants
// ---------------------------------------------------------------------------
constexpr int H    = 2048;
constexpr int NH   = 16;
constexpr int NOPE = 128;
constexpr int ROPE = 64;
constexpr int VD   = 128;
constexpr int QR   = 1024;
constexpr int KVR  = 512;
constexpr int BB   = 2;       // batch
constexpr int S    = 2048;    // seq len
constexpr int T    = BB * S;  // 4096 tokens
constexpr float EPS = 1e-6f;
constexpr float SM_SCALE2 = 0.10412105626079532f;         // (1/sqrt(192)) * log2(e)
constexpr float MASK2 = -1.4426950408889634e9f;           // -1e9 * log2(e)

// ---------------------------------------------------------------------------
// Device scratch (allocation-free rule: __device__ globals)
// ---------------------------------------------------------------------------
__device__ float g_cq   [T * QR];
__device__ float g_ckv  [T * KVR];
__device__ float g_qrope_f[T * NH * ROPE];   // GEMM fp32 out (pre-rope)
__device__ float g_krope_f[T * ROPE];
__device__ float g_v    [T * NH * VD];       // fp32, tf32-rounded
__device__ float g_attn [T * NH * VD];
__device__ float g_ctab [S * (ROPE / 2)];
__device__ float g_stab [S * (ROPE / 2)];
__device__ __align__(16) __half g_qnope_h[T * NH * NOPE];
__device__ __align__(16) __half g_knope_h[T * NH * NOPE];
__device__ __align__(16) __half g_qrope_h[T * NH * ROPE];
__device__ __align__(16) __half g_krope_h[T * ROPE];

// ---------------------------------------------------------------------------
// tf32 / fp16 helpers
// ---------------------------------------------------------------------------
__device__ __forceinline__ float to_tf32(float x) {
    uint32_t u;
    asm("cvt.rna.tf32.f32 %0, %1;" : "=r"(u) : "f"(x));
    return __uint_as_float(u);
}
__device__ __forceinline__ float4 to_tf32x4(float4 v) {
    return make_float4(to_tf32(v.x), to_tf32(v.y), to_tf32(v.z), to_tf32(v.w));
}

__device__ __forceinline__ void mma_tf32(float& c0, float& c1, float& c2, float& c3,
                                         float a0, float a1, float a2, float a3,
                                         float b0, float b1)
{
    uint32_t ua0 = __float_as_uint(a0), ua1 = __float_as_uint(a1);
    uint32_t ua2 = __float_as_uint(a2), ua3 = __float_as_uint(a3);
    uint32_t ub0 = __float_as_uint(b0), ub1 = __float_as_uint(b1);
    asm volatile(
        "mma.sync.aligned.m16n8k8.row.col.f32.tf32.tf32.f32 "
        "{%0,%1,%2,%3}, {%4,%5,%6,%7}, {%8,%9}, {%0,%1,%2,%3};\n"
        : "+f"(c0), "+f"(c1), "+f"(c2), "+f"(c3)
        : "r"(ua0), "r"(ua1), "r"(ua2), "r"(ua3), "r"(ub0), "r"(ub1));
}

__device__ __forceinline__ void mma_f16(float& c0, float& c1, float& c2, float& c3,
                                        uint32_t a0, uint32_t a1, uint32_t a2, uint32_t a3,
                                        uint32_t b0, uint32_t b1)
{
    asm volatile(
        "mma.sync.aligned.m16n8k16.row.col.f32.f16.f16.f32 "
        "{%0,%1,%2,%3}, {%4,%5,%6,%7}, {%8,%9}, {%0,%1,%2,%3};\n"
        : "+f"(c0), "+f"(c1), "+f"(c2), "+f"(c3)
        : "r"(a0), "r"(a1), "r"(a2), "r"(a3), "r"(b0), "r"(b1));
}

// fp16 fragment smem stores (m16n8k16). Values are packed half2 = one mma reg.
// A-frag: F[mtile][kstep(12)][slot(4)][lane(32)]; k multiple of 8, 8 halves.
__device__ __forceinline__ void st_afrag_h(uint32_t* F, int m, int k, uint4 v) {
    int slot = ((m >> 3) & 1) + (((k >> 3) & 1) << 1);
    uint32_t* dst = F + ((((m >> 4) * 12 + (k >> 4)) * 4 + slot) << 5) + (m & 7) * 4;
    *(uint4*)dst = v;
}
// B-frag: F[ntile][kstep(12)][slot(2)][lane(32)]
__device__ __forceinline__ void st_bfrag_h(uint32_t* F, int n, int k, uint4 v) {
    int slot = (k >> 3) & 1;
    uint32_t* dst = F + ((((n >> 3) * 12 + (k >> 4)) * 2 + slot) << 5) + (n & 7) * 4;
    *(uint4*)dst = v;
}

// ---------------------------------------------------------------------------
// tf32 tensor-core GEMM: C[M,N] = A[M,K] @ B[K,N].
// round_out==1 -> fp32 tf32-rounded; Ch != nullptr -> write fp16 instead.
// ---------------------------------------------------------------------------
constexpr int AS_STRIDE = 20;
constexpr int BS_STRIDE = 136;

__global__ void __launch_bounds__(256)
tf32_gemm_kernel(const float* __restrict__ A, const float* __restrict__ B,
                 float* __restrict__ C, __half* __restrict__ Ch,
                 int M, int N, int K, int round_out)
{
    __shared__ float As[2][128][AS_STRIDE];
    __shared__ float Bs[2][16][BS_STRIDE];

    const int tid  = threadIdx.x;
    const int lane = tid & 31;
    const int warp = tid >> 5;
    const int qid  = lane >> 2;
    const int rid  = lane & 3;
    const int wr   = (warp >> 2) * 64;
    const int wc   = (warp & 3) * 32;

    const int rowBase = blockIdx.y * 128;
    const int colBase = blockIdx.x * 128;

    const int ar0 = tid >> 2;
    const int ar1 = ar0 + 64;
    const int ac  = (tid & 3) * 4;
    const int bk0 = tid >> 5;
    const int bk1 = bk0 + 8;
    const int bn  = (tid & 31) * 4;
    const int gn  = colBase + bn;
    const bool bok = (gn < N);

    float acc[4][4][4];
#pragma unroll
    for (int i = 0; i < 4; i++)
#pragma unroll
        for (int j = 0; j < 4; j++)
#pragma unroll
            for (int c = 0; c < 4; c++) acc[i][j][c] = 0.f;

    const int nt = K / 16;
    float4 ra0, ra1, rb0, rb1;

    ra0 = *(const float4*)&A[(size_t)(rowBase + ar0) * K + ac];
    ra1 = *(const float4*)&A[(size_t)(rowBase + ar1) * K + ac];
    rb0 = bok ? *(const float4*)&B[(size_t)bk0 * N + gn] : make_float4(0,0,0,0);
    rb1 = bok ? *(const float4*)&B[(size_t)bk1 * N + gn] : make_float4(0,0,0,0);
    *(float4*)&As[0][ar0][ac] = to_tf32x4(ra0);
    *(float4*)&As[0][ar1][ac] = to_tf32x4(ra1);
    *(float4*)&Bs[0][bk0][bn] = to_tf32x4(rb0);
    *(float4*)&Bs[0][bk1][bn] = to_tf32x4(rb1);
    __syncthreads();

    for (int t = 0; t < nt; t++) {
        const int buf = t & 1;

        if (t + 1 < nt) {
            const int k0 = (t + 1) * 16;
            ra0 = *(const float4*)&A[(size_t)(rowBase + ar0) * K + k0 + ac];
            ra1 = *(const float4*)&A[(size_t)(rowBase + ar1) * K + k0 + ac];
            rb0 = bok ? *(const float4*)&B[(size_t)(k0 + bk0) * N + gn] : make_float4(0,0,0,0);
            rb1 = bok ? *(const float4*)&B[(size_t)(k0 + bk1) * N + gn] : make_float4(0,0,0,0);
        }

#pragma unroll
        for (int ks = 0; ks < 16; ks += 8) {
            float a[4][4], b[4][2];
#pragma unroll
            for (int i = 0; i < 4; i++) {
                const float* p0 = &As[buf][wr + i * 16 + qid][ks + rid];
                const float* p1 = &As[buf][wr + i * 16 + qid + 8][ks + rid];
                a[i][0] = p0[0];
                a[i][1] = p1[0];
                a[i][2] = p0[4];
                a[i][3] = p1[4];
            }
#pragma unroll
            for (int j = 0; j < 4; j++) {
                b[j][0] = Bs[buf][ks + rid][wc + j * 8 + qid];
                b[j][1] = Bs[buf][ks + rid + 4][wc + j * 8 + qid];
            }
#pragma unroll
            for (int i = 0; i < 4; i++)
#pragma unroll
                for (int j = 0; j < 4; j++)
                    mma_tf32(acc[i][j][0], acc[i][j][1], acc[i][j][2], acc[i][j][3],
                             a[i][0], a[i][1], a[i][2], a[i][3],
                             b[j][0], b[j][1]);
        }

        if (t + 1 < nt) {
            const int nb = (t + 1) & 1;
            *(float4*)&As[nb][ar0][ac] = to_tf32x4(ra0);
            *(float4*)&As[nb][ar1][ac] = to_tf32x4(ra1);
            *(float4*)&Bs[nb][bk0][bn] = to_tf32x4(rb0);
            *(float4*)&Bs[nb][bk1][bn] = to_tf32x4(rb1);
        }
        __syncthreads();
    }

#pragma unroll
    for (int i = 0; i < 4; i++) {
        const int r0 = rowBase + wr + i * 16 + qid;
#pragma unroll
        for (int j = 0; j < 4; j++) {
            const int col = colBase + wc + j * 8 + rid * 2;
            if (col < N) {
                if (Ch) {
                    __half2 h0 = __floats2half2_rn(acc[i][j][0], acc[i][j][1]);
                    __half2 h1 = __floats2half2_rn(acc[i][j][2], acc[i][j][3]);
                    *(__half2*)&Ch[(size_t)r0 * N + col]       = h0;
                    *(__half2*)&Ch[(size_t)(r0 + 8) * N + col] = h1;
                } else {
                    float2 v0 = make_float2(acc[i][j][0], acc[i][j][1]);
                    float2 v1 = make_float2(acc[i][j][2], acc[i][j][3]);
                    if (round_out) {
                        v0.x = to_tf32(v0.x); v0.y = to_tf32(v0.y);
                        v1.x = to_tf32(v1.x); v1.y = to_tf32(v1.y);
                    }
                    *(float2*)&C[(size_t)r0 * N + col]       = v0;
                    *(float2*)&C[(size_t)(r0 + 8) * N + col] = v1;
                }
            }
        }
    }
}

// ---------------------------------------------------------------------------
// RMSNorm (in place)
// ---------------------------------------------------------------------------
__global__ void rmsnorm_kernel(float* __restrict__ x,
                               const float* __restrict__ scale, int D)
{
    __shared__ float red[32];
    float* p = x + (size_t)blockIdx.x * D;

    float ss = 0.f;
    for (int d = threadIdx.x; d < D; d += blockDim.x) {
        float v = p[d];
        ss += v * v;
    }
#pragma unroll
    for (int o = 16; o; o >>= 1) ss += __shfl_xor_sync(0xffffffffu, ss, o);
    if ((threadIdx.x & 31) == 0) red[threadIdx.x >> 5] = ss;
    __syncthreads();
    if (threadIdx.x < 32) {
        float v = (threadIdx.x < (blockDim.x >> 5)) ? red[threadIdx.x] : 0.f;
#pragma unroll
        for (int o = 16; o; o >>= 1) v += __shfl_xor_sync(0xffffffffu, v, o);
        if (threadIdx.x == 0) red[0] = v;
    }
    __syncthreads();
    float inv = rsqrtf(red[0] / (float)D + EPS);
    for (int d = threadIdx.x; d < D; d += blockDim.x)
        p[d] = p[d] * inv * scale[d];
}

// ---------------------------------------------------------------------------
// RoPE tables / application (rope kernels emit fp16 for the attention mma)
// ---------------------------------------------------------------------------
__global__ void rope_table_kernel(float* __restrict__ ctab, float* __restrict__ stab)
{
    int idx = blockIdx.x * blockDim.x + threadIdx.x;
    if (idx >= S * (ROPE / 2)) return;
    int i = idx % (ROPE / 2);
    int s = idx / (ROPE / 2);
    float freq = (float)pow(10000.0, -((double)(2 * i)) / (double)ROPE);
    float ang  = (float)s * freq;
    double a   = (double)ang;
    ctab[idx] = (float)cos(a);
    stab[idx] = (float)sin(a);
}

__global__ void rope_q_kernel(const float* __restrict__ qf, __half* __restrict__ qh,
                              const float* __restrict__ ctab,
                              const float* __restrict__ stab)
{
    int idx = blockIdx.x * blockDim.x + threadIdx.x;
    if (idx >= T * NH * (ROPE / 2)) return;
    int i   = idx & 31;
    int rem = idx >> 5;
    int h   = rem & (NH - 1);
    int tok = rem >> 4;
    int s   = tok & (S - 1);
    float c  = ctab[s * 32 + i];
    float sn = stab[s * 32 + i];
    size_t off = (size_t)tok * (NH * ROPE) + h * ROPE + 2 * i;
    float x1 = qf[off], x2 = qf[off + 1];
    *(__half2*)&qh[off] = __floats2half2_rn(x1 * c - x2 * sn, x1 * sn + x2 * c);
}

__global__ void rope_k_kernel(const float* __restrict__ kf, __half* __restrict__ kh,
                              const float* __restrict__ ctab,
                              const float* __restrict__ stab)
{
    int idx = blockIdx.x * blockDim.x + threadIdx.x;
    if (idx >= T * (ROPE / 2)) return;
    int i   = idx & 31;
    int tok = idx >> 5;
    int s   = tok & (S - 1);
    float c  = ctab[s * 32 + i];
    float sn = stab[s * 32 + i];
    size_t off = (size_t)tok * ROPE + 2 * i;
    float x1 = kf[off], x2 = kf[off + 1];
    *(__half2*)&kh[off] = __floats2half2_rn((x1 * c - x2 * sn) * 0.0625f,
                                            (x1 * sn + x2 * c) * 0.0625f);
}

// ---------------------------------------------------------------------------
// Flash attention: BQ=128, 512 threads. QK on fp16 m16n8k16 (halved mma+LDS),
// PV on proven tf32 path. In-register softmax; skewed pipeline; reg prefetch.
// ---------------------------------------------------------------------------
constexpr int BQ  = 128;
constexpr int BKT = 64;
constexpr int VSTR = 136;
constexpr int PSTR = 68;

struct AttnSmem {
    uint32_t Qf[8 * 12 * 4 * 32];   // fp16 A-frag: [mtile][kstep][slot][lane] 49.2KB
    uint32_t Kf[8 * 12 * 2 * 32];   // fp16 B-frag: [ntile][kstep][slot][lane] 24.6KB
    float V[BKT][VSTR];             // 34.8KB
    float P[BQ][PSTR];              // 34.8KB
    float rowmax[2][BQ];
    float rowsum[2][BQ];
};

__global__ void __launch_bounds__(512)
attn_kernel(const __half* __restrict__ qn, const __half* __restrict__ qr,
            const __half* __restrict__ kn, const __half* __restrict__ kr,
            const float* __restrict__ v,  float* __restrict__ out)
{
    extern __shared__ char smraw[];
    AttnSmem& sm = *reinterpret_cast<AttnSmem*>(smraw);

    const int qt = (gridDim.x - 1) - blockIdx.x;   // heavy blocks first
    const int h  = blockIdx.y;
    const int b  = blockIdx.z;
    const int tid = threadIdx.x;
    const int lane = tid & 31;
    const int warp = tid >> 5;
    const int qid  = lane >> 2;
    const int rid  = lane & 3;
    const int qb = b * S + qt * BQ;

    const int mtile = warp & 7;
    const int half  = warp >> 3;         // column half (0 or 1)
    const int ntb   = half * 4;
    const int row0 = mtile * 16 + qid;
    const int nbv  = half * 64;

    // staging indices: K tile (fp16) and V tile (fp32)
    const int krow = tid & 63;           // K row (64 rows)
    const int kg   = tid >> 6;           // 0..7 (8-half group)
    const int vrn[4] = { tid >> 5, (tid + 512) >> 5, (tid + 1024) >> 5, (tid + 1536) >> 5 };
    const int vcn    = (tid & 31) * 4;

    // ---- stage Q tile [128 x 192] halves into fp16 A-frag layout ----
    for (int idx = tid; idx < BQ * 16; idx += 512) {        // nope: 16 groups/row
        int r = idx & 127, g = idx >> 7;
        uint4 u = *(const uint4*)&qn[(size_t)(qb + r) * (NH * NOPE) + h * NOPE + g * 8];
        st_afrag_h(sm.Qf, r, g * 8, u);
    }
    for (int idx = tid; idx < BQ * 8; idx += 512) {         // rope: 8 groups/row
        int r = idx & 127, g = idx >> 7;
        uint4 u = *(const uint4*)&qr[(size_t)(qb + r) * (NH * ROPE) + h * ROPE + g * 8];
        st_afrag_h(sm.Qf, r, 128 + g * 8, u);
    }

    // per-thread online-softmax state (log2 domain)
    float m0 = -1e30f, m1 = -1e30f, l0 = 0.f, l1 = 0.f;
    float acc[8][4];
#pragma unroll
    for (int j = 0; j < 8; j++)
#pragma unroll
        for (int c = 0; c < 4; c++) acc[j][c] = 0.f;

    const int nkt = 2 * qt + 2;

    // ---- prologue: load tile 0 regs, stage Kf(0), then prefetch K(1) ----
    uint4 kb[3];      // 2 nope groups + 1 rope group (fp16)
    float4 vb[4];
    {
        const int kbT = b * S;
        kb[0] = *(const uint4*)&kn[(size_t)(kbT + krow) * (NH * NOPE) + h * NOPE + kg * 8];
        kb[1] = *(const uint4*)&kn[(size_t)(kbT + krow) * (NH * NOPE) + h * NOPE + kg * 8 + 64];
        kb[2] = *(const uint4*)&kr[(size_t)(kbT + krow) * ROPE + kg * 8];
#pragma unroll
        for (int i = 0; i < 4; i++)
            vb[i] = *(const float4*)&v[(size_t)(kbT + vrn[i]) * (NH * VD) + h * VD + vcn];
    }
    st_bfrag_h(sm.Kf, krow, kg * 8, kb[0]);
    st_bfrag_h(sm.Kf, krow, kg * 8 + 64, kb[1]);
    st_bfrag_h(sm.Kf, krow, 128 + kg * 8, kb[2]);
    __syncthreads();            // Qf + Kf(0) visible
    if (1 < nkt) {
        const int kbT = b * S + BKT;
        kb[0] = *(const uint4*)&kn[(size_t)(kbT + krow) * (NH * NOPE) + h * NOPE + kg * 8];
        kb[1] = *(const uint4*)&kn[(size_t)(kbT + krow) * (NH * NOPE) + h * NOPE + kg * 8 + 64];
        kb[2] = *(const uint4*)&kr[(size_t)(kbT + krow) * ROPE + kg * 8];
    }

    for (int kt = 0; kt < nkt; kt++) {
        // ---- stage V(kt) (buffer free since barC of prev iter) ----
#pragma unroll
        for (int i = 0; i < 4; i++) *(float4*)&sm.V[vrn[i]][vcn] = vb[i];

        // ---- QK(kt) via fp16 m16n8k16 -> scores stay in registers ----
        float c[4][4];
#pragma unroll
        for (int j = 0; j < 4; j++)
#pragma unroll
            for (int cc = 0; cc < 4; cc++) c[j][cc] = 0.f;

#pragma unroll
        for (int ks = 0; ks < 12; ks++) {
            const uint32_t* ap = &sm.Qf[(((mtile * 12 + ks) * 4) << 5) + lane];
            uint32_t a0 = ap[0], a1 = ap[32], a2 = ap[64], a3 = ap[96];
#pragma unroll
            for (int j = 0; j < 4; j++) {
                const uint32_t* bp = &sm.Kf[((((ntb + j) * 12 + ks) * 2) << 5) + lane];
                mma_f16(c[j][0], c[j][1], c[j][2], c[j][3],
                        a0, a1, a2, a3, bp[0], bp[32]);
            }
        }

        // scale + mask in registers
        {
            const bool diag = (kt >= 2 * qt);
#pragma unroll
            for (int j = 0; j < 4; j++) {
                int col = (ntb + j) * 8 + rid * 2;
                int ki0 = kt * BKT + col;
                c[j][0] *= SM_SCALE2; c[j][1] *= SM_SCALE2;
                c[j][2] *= SM_SCALE2; c[j][3] *= SM_SCALE2;
                if (diag) {
                    int qi0 = qt * BQ + row0;
                    int qi1 = qi0 + 8;
                    if (ki0     > qi0) c[j][0] = MASK2;
                    if (ki0 + 1 > qi0) c[j][1] = MASK2;
                    if (ki0     > qi1) c[j][2] = MASK2;
                    if (ki0 + 1 > qi1) c[j][3] = MASK2;
                }
            }
        }

        // per-row max over this warp's 32 columns
        {
            float mx0 = fmaxf(fmaxf(c[0][0], c[0][1]), fmaxf(c[1][0], c[1][1]));
            mx0 = fmaxf(mx0, fmaxf(fmaxf(c[2][0], c[2][1]), fmaxf(c[3][0], c[3][1])));
            float mx1 = fmaxf(fmaxf(c[0][2], c[0][3]), fmaxf(c[1][2], c[1][3]));
            mx1 = fmaxf(mx1, fmaxf(fmaxf(c[2][2], c[2][3]), fmaxf(c[3][2], c[3][3])));
            mx0 = fmaxf(mx0, __shfl_xor_sync(0xffffffffu, mx0, 1));
            mx0 = fmaxf(mx0, __shfl_xor_sync(0xffffffffu, mx0, 2));
            mx1 = fmaxf(mx1, __shfl_xor_sync(0xffffffffu, mx1, 1));
            mx1 = fmaxf(mx1, __shfl_xor_sync(0xffffffffu, mx1, 2));
            if (rid == 0) {
                sm.rowmax[half][row0]     = mx0;
                sm.rowmax[half][row0 + 8] = mx1;
            }
        }
        __syncthreads();   // barA: rowmax halves + V(kt) stores visible

        // ---- combine max, exp from registers, write tf32 P, partial sums ----
        float al0, al1;
        {
            float f0 = fmaxf(sm.rowmax[0][row0],     sm.rowmax[1][row0]);
            float f1 = fmaxf(sm.rowmax[0][row0 + 8], sm.rowmax[1][row0 + 8]);
            float mn0 = fmaxf(m0, f0);
            float mn1 = fmaxf(m1, f1);
            al0 = exp2f(m0 - mn0);
            al1 = exp2f(m1 - mn1);
            m0 = mn0; m1 = mn1;

            float ps0 = 0.f, ps1 = 0.f;
#pragma unroll
            for (int j = 0; j < 4; j++) {
                float e0 = exp2f(c[j][0] - mn0);
                float e1 = exp2f(c[j][1] - mn0);
                float e2 = exp2f(c[j][2] - mn1);
                float e3 = exp2f(c[j][3] - mn1);
                ps0 += e0 + e1;
                ps1 += e2 + e3;
                int col = (ntb + j) * 8 + rid * 2;
                *(float2*)&sm.P[row0][col]     = make_float2(to_tf32(e0), to_tf32(e1));
                *(float2*)&sm.P[row0 + 8][col] = make_float2(to_tf32(e2), to_tf32(e3));
            }
            ps0 += __shfl_xor_sync(0xffffffffu, ps0, 1);
            ps0 += __shfl_xor_sync(0xffffffffu, ps0, 2);
            ps1 += __shfl_xor_sync(0xffffffffu, ps1, 1);
            ps1 += __shfl_xor_sync(0xffffffffu, ps1, 2);
            if (rid == 0) {
                sm.rowsum[half][row0]     = ps0;
                sm.rowsum[half][row0 + 8] = ps1;
            }
        }

        // ---- stage Kf(kt+1); prefetch V(kt+1), K(kt+2) regs ----
        if (kt + 1 < nkt) {
            const int vT = b * S + (kt + 1) * BKT;
#pragma unroll
            for (int i = 0; i < 4; i++)
                vb[i] = *(const float4*)&v[(size_t)(vT + vrn[i]) * (NH * VD) + h * VD + vcn];
            st_bfrag_h(sm.Kf, krow, kg * 8, kb[0]);
            st_bfrag_h(sm.Kf, krow, kg * 8 + 64, kb[1]);
            st_bfrag_h(sm.Kf, krow, 128 + kg * 8, kb[2]);
            if (kt + 2 < nkt) {
                const int kT = b * S + (kt + 2) * BKT;
                kb[0] = *(const uint4*)&kn[(size_t)(kT + krow) * (NH * NOPE) + h * NOPE + kg * 8];
                kb[1] = *(const uint4*)&kn[(size_t)(kT + krow) * (NH * NOPE) + h * NOPE + kg * 8 + 64];
                kb[2] = *(const uint4*)&kr[(size_t)(kT + krow) * ROPE + kg * 8];
            }
        }
        __syncthreads();   // barB: P + rowsum + Kf(kt+1) visible

        // ---- l update + PV(kt) via tf32 mma (unchanged proven path) ----
        {
            l0 = l0 * al0 + (sm.rowsum[0][row0]     + sm.rowsum[1][row0]);
            l1 = l1 * al1 + (sm.rowsum[0][row0 + 8] + sm.rowsum[1][row0 + 8]);
#pragma unroll
            for (int j = 0; j < 8; j++) {
                acc[j][0] *= al0; acc[j][1] *= al0;
                acc[j][2] *= al1; acc[j][3] *= al1;
            }
#pragma unroll
            for (int ks = 0; ks < 8; ks++) {
                const float a0 = sm.P[row0]    [ks * 8 + rid];
                const float a1 = sm.P[row0 + 8][ks * 8 + rid];
                const float a2 = sm.P[row0]    [ks * 8 + rid + 4];
                const float a3 = sm.P[row0 + 8][ks * 8 + rid + 4];
#pragma unroll
                for (int j = 0; j < 8; j++) {
                    const float b0 = sm.V[ks * 8 + rid]    [nbv + j * 8 + qid];
                    const float b1 = sm.V[ks * 8 + rid + 4][nbv + j * 8 + qid];
                    mma_tf32(acc[j][0], acc[j][1], acc[j][2], acc[j][3],
                             a0, a1, a2, a3, b0, b1);
                }
            }
        }
        __syncthreads();   // barC: PV(kt) drained; V/P/rowmax free
    }

    // ---- epilogue: scale by 1/l, write out ----
    {
        const float il0 = 1.f / l0;
        const float il1 = 1.f / l1;
        const int tok0 = qb + row0;
        const int tok1 = tok0 + 8;
#pragma unroll
        for (int j = 0; j < 8; j++) {
            const int col = nbv + j * 8 + rid * 2;
            *(float2*)&out[(size_t)tok0 * (NH * VD) + h * VD + col] =
                make_float2(acc[j][0] * il0, acc[j][1] * il0);
            *(float2*)&out[(size_t)tok1 * (NH * VD) + h * VD + col] =
                make_float2(acc[j][2] * il1, acc[j][3] * il1);
        }
    }
}

// ---------------------------------------------------------------------------
// Launch (Q path and KV path forked onto concurrent streams inside capture)
// ---------------------------------------------------------------------------
static void launch_gemm_s(cudaStream_t s, const float* A, const float* B, float* C,
                          int M, int N, int K, int round_out = 0, __half* Ch = nullptr)
{
    dim3 grid((N + 127) / 128, (M + 127) / 128);
    tf32_gemm_kernel<<<grid, 256, 0, s>>>(A, B, C, Ch, M, N, K, round_out);
}

extern "C" void kernel_launch(void* const* d_in, const int* in_sizes, int n_in,
                              void* d_out, int out_size)
{
    const float* x         = (const float*)d_in[0];
    const float* W_cq      = (const float*)d_in[1];
    const float* q_scale   = (const float*)d_in[2];
    const float* W_dq_nope = (const float*)d_in[3];
    const float* W_dq_rope = (const float*)d_in[4];
    const float* W_ckv     = (const float*)d_in[5];
    const float* kv_scale  = (const float*)d_in[6];
    const float* W_dk_nope = (const float*)d_in[7];
    const float* W_dv      = (const float*)d_in[8];
    const float* W_krope   = (const float*)d_in[9];
    const float* W_o       = (const float*)d_in[10];
    float* out = (float*)d_out;

    float *cq, *ckv, *qrf, *krf, *vv, *att, *ctab, *stab;
    __half *qnh, *knh, *qrh, *krh;
    cudaGetSymbolAddress((void**)&cq,   g_cq);
    cudaGetSymbolAddress((void**)&ckv,  g_ckv);
    cudaGetSymbolAddress((void**)&qrf,  g_qrope_f);
    cudaGetSymbolAddress((void**)&krf,  g_krope_f);
    cudaGetSymbolAddress((void**)&vv,   g_v);
    cudaGetSymbolAddress((void**)&att,  g_attn);
    cudaGetSymbolAddress((void**)&ctab, g_ctab);
    cudaGetSymbolAddress((void**)&stab, g_stab);
    cudaGetSymbolAddress((void**)&qnh,  g_qnope_h);
    cudaGetSymbolAddress((void**)&knh,  g_knope_h);
    cudaGetSymbolAddress((void**)&qrh,  g_qrope_h);
    cudaGetSymbolAddress((void**)&krh,  g_krope_h);

    // Fork/join machinery (host-only cost; harness times graph replays).
    cudaStream_t s0 = 0;
    cudaStream_t skv;
    cudaEvent_t ev_fork, ev_kv;
    cudaStreamCreateWithFlags(&skv, cudaStreamNonBlocking);
    cudaEventCreateWithFlags(&ev_fork, cudaEventDisableTiming);
    cudaEventCreateWithFlags(&ev_kv,  cudaEventDisableTiming);

    // RoPE tables (needed by both paths)
    rope_table_kernel<<<(S * 32 + 255) / 256, 256, 0, s0>>>(ctab, stab);

    // ---- fork: KV path on skv ----
    cudaEventRecord(ev_fork, s0);
    cudaStreamWaitEvent(skv, ev_fork, 0);

    // KV path (skv)
    launch_gemm_s(skv, x, W_krope, krf, T, ROPE, H);
    rope_k_kernel<<<(T * 32 + 255) / 256, 256, 0, skv>>>(krf, krh, ctab, stab);
    launch_gemm_s(skv, x, W_ckv, ckv, T, KVR, H);
    rmsnorm_kernel<<<T, 256, 0, skv>>>(ckv, kv_scale, KVR);
    launch_gemm_s(skv, ckv, W_dk_nope, nullptr, T, NH * NOPE, KVR, 0, knh); // fp16 out
    launch_gemm_s(skv, ckv, W_dv, vv, T, NH * VD, KVR, 1);                  // tf32 out
    cudaEventRecord(ev_kv, skv);

    // Q path (s0)
    launch_gemm_s(s0, x, W_cq, cq, T, QR, H);
    rmsnorm_kernel<<<T, 256, 0, s0>>>(cq, q_scale, QR);
    launch_gemm_s(s0, cq, W_dq_nope, nullptr, T, NH * NOPE, QR, 0, qnh);    // fp16 out
    launch_gemm_s(s0, cq, W_dq_rope, qrf, T, NH * ROPE, QR);
    rope_q_kernel<<<(T * NH * 32 + 255) / 256, 256, 0, s0>>>(qrf, qrh, ctab, stab);

    // ---- join ----
    cudaStreamWaitEvent(s0, ev_kv, 0);

    // Attention
    cudaFuncSetAttribute((const void*)attn_kernel,
                         cudaFuncAttributeMaxDynamicSharedMemorySize,
                         (int)sizeof(AttnSmem));
    attn_kernel<<<dim3(S / BQ, NH, BB), 512, sizeof(AttnSmem), s0>>>(qnh, qrh, knh, krh, vv, att);

    // Output projection
    launch_gemm_s(s0, att, W_o, out, T, H, NH * VD);
}

// round 16
// speedup vs baseline: 1.6612x; 1.0550x over previous
#include <cuda_runtime.h>
#include <cuda_fp16.h>
#include <math.h>
#include <stdint.h>

// ---------------------------------------------------------------------------
// Problem constants
// ---------------------------------------------------------------------------
constexpr int H    = 2048;
constexpr int NH   = 16;
constexpr int NOPE = 128;
constexpr int ROPE = 64;
constexpr int VD   = 128;
constexpr int QR   = 1024;
constexpr int KVR  = 512;
constexpr int BB   = 2;       // batch
constexpr int S    = 2048;    // seq len
constexpr int T    = BB * S;  // 4096 tokens
constexpr float EPS = 1e-6f;
constexpr float SM_SCALE2 = 0.10412105626079532f;         // (1/sqrt(192)) * log2(e)
constexpr float MASK2 = -1.4426950408889634e9f;           // -1e9 * log2(e)

// ---------------------------------------------------------------------------
// Device scratch (allocation-free rule: __device__ globals)
// ---------------------------------------------------------------------------
__device__ float g_cq   [T * QR];
__device__ float g_ckv  [T * KVR];
__device__ float g_qrope_f[T * NH * ROPE];   // GEMM fp32 out (pre-rope)
__device__ float g_krope_f[T * ROPE];
__device__ float g_attn [T * NH * VD];
__device__ float g_ctab [S * (ROPE / 2)];
__device__ float g_stab [S * (ROPE / 2)];
__device__ __align__(16) __half g_qnope_h[T * NH * NOPE];
__device__ __align__(16) __half g_knope_h[T * NH * NOPE];
__device__ __align__(16) __half g_qrope_h[T * NH * ROPE];
__device__ __align__(16) __half g_krope_h[T * ROPE];
__device__ __align__(16) __half g_v_h    [T * NH * VD];

// ---------------------------------------------------------------------------
// tf32 / fp16 helpers
// ---------------------------------------------------------------------------
__device__ __forceinline__ float to_tf32(float x) {
    uint32_t u;
    asm("cvt.rna.tf32.f32 %0, %1;" : "=r"(u) : "f"(x));
    return __uint_as_float(u);
}
__device__ __forceinline__ float4 to_tf32x4(float4 v) {
    return make_float4(to_tf32(v.x), to_tf32(v.y), to_tf32(v.z), to_tf32(v.w));
}
__device__ __forceinline__ uint32_t h2_as_u32(__half2 h) {
    return *reinterpret_cast<uint32_t*>(&h);
}

__device__ __forceinline__ void mma_tf32(float& c0, float& c1, float& c2, float& c3,
                                         float a0, float a1, float a2, float a3,
                                         float b0, float b1)
{
    uint32_t ua0 = __float_as_uint(a0), ua1 = __float_as_uint(a1);
    uint32_t ua2 = __float_as_uint(a2), ua3 = __float_as_uint(a3);
    uint32_t ub0 = __float_as_uint(b0), ub1 = __float_as_uint(b1);
    asm volatile(
        "mma.sync.aligned.m16n8k8.row.col.f32.tf32.tf32.f32 "
        "{%0,%1,%2,%3}, {%4,%5,%6,%7}, {%8,%9}, {%0,%1,%2,%3};\n"
        : "+f"(c0), "+f"(c1), "+f"(c2), "+f"(c3)
        : "r"(ua0), "r"(ua1), "r"(ua2), "r"(ua3), "r"(ub0), "r"(ub1));
}

__device__ __forceinline__ void mma_f16(float& c0, float& c1, float& c2, float& c3,
                                        uint32_t a0, uint32_t a1, uint32_t a2, uint32_t a3,
                                        uint32_t b0, uint32_t b1)
{
    asm volatile(
        "mma.sync.aligned.m16n8k16.row.col.f32.f16.f16.f32 "
        "{%0,%1,%2,%3}, {%4,%5,%6,%7}, {%8,%9}, {%0,%1,%2,%3};\n"
        : "+f"(c0), "+f"(c1), "+f"(c2), "+f"(c3)
        : "r"(a0), "r"(a1), "r"(a2), "r"(a3), "r"(b0), "r"(b1));
}

__device__ __forceinline__ uint32_t prmt(uint32_t a, uint32_t b, uint32_t sel) {
    uint32_t r;
    asm("prmt.b32 %0, %1, %2, %3;" : "=r"(r) : "r"(a), "r"(b), "r"(sel));
    return r;
}

// fp16 fragment smem stores for QK (m16n8k16).
__device__ __forceinline__ void st_afrag_h(uint32_t* F, int m, int k, uint4 v) {
    int slot = ((m >> 3) & 1) + (((k >> 3) & 1) << 1);
    uint32_t* dst = F + ((((m >> 4) * 12 + (k >> 4)) * 4 + slot) << 5) + (m & 7) * 4;
    *(uint4*)dst = v;
}
__device__ __forceinline__ void st_bfrag_h(uint32_t* F, int n, int k, uint4 v) {
    int slot = (k >> 3) & 1;
    uint32_t* dst = F + ((((n >> 3) * 12 + (k >> 4)) * 2 + slot) << 5) + (n & 7) * 4;
    *(uint4*)dst = v;
}

// ---------------------------------------------------------------------------
// tf32 tensor-core GEMM: C[M,N] = A[M,K] @ B[K,N].
// round_out==1 -> fp32 tf32-rounded; Ch != nullptr -> write fp16 instead.
// ---------------------------------------------------------------------------
constexpr int AS_STRIDE = 20;
constexpr int BS_STRIDE = 136;

__global__ void __launch_bounds__(256)
tf32_gemm_kernel(const float* __restrict__ A, const float* __restrict__ B,
                 float* __restrict__ C, __half* __restrict__ Ch,
                 int M, int N, int K, int round_out)
{
    __shared__ float As[2][128][AS_STRIDE];
    __shared__ float Bs[2][16][BS_STRIDE];

    const int tid  = threadIdx.x;
    const int lane = tid & 31;
    const int warp = tid >> 5;
    const int qid  = lane >> 2;
    const int rid  = lane & 3;
    const int wr   = (warp >> 2) * 64;
    const int wc   = (warp & 3) * 32;

    const int rowBase = blockIdx.y * 128;
    const int colBase = blockIdx.x * 128;

    const int ar0 = tid >> 2;
    const int ar1 = ar0 + 64;
    const int ac  = (tid & 3) * 4;
    const int bk0 = tid >> 5;
    const int bk1 = bk0 + 8;
    const int bn  = (tid & 31) * 4;
    const int gn  = colBase + bn;
    const bool bok = (gn < N);

    float acc[4][4][4];
#pragma unroll
    for (int i = 0; i < 4; i++)
#pragma unroll
        for (int j = 0; j < 4; j++)
#pragma unroll
            for (int c = 0; c < 4; c++) acc[i][j][c] = 0.f;

    const int nt = K / 16;
    float4 ra0, ra1, rb0, rb1;

    ra0 = *(const float4*)&A[(size_t)(rowBase + ar0) * K + ac];
    ra1 = *(const float4*)&A[(size_t)(rowBase + ar1) * K + ac];
    rb0 = bok ? *(const float4*)&B[(size_t)bk0 * N + gn] : make_float4(0,0,0,0);
    rb1 = bok ? *(const float4*)&B[(size_t)bk1 * N + gn] : make_float4(0,0,0,0);
    *(float4*)&As[0][ar0][ac] = to_tf32x4(ra0);
    *(float4*)&As[0][ar1][ac] = to_tf32x4(ra1);
    *(float4*)&Bs[0][bk0][bn] = to_tf32x4(rb0);
    *(float4*)&Bs[0][bk1][bn] = to_tf32x4(rb1);
    __syncthreads();

    for (int t = 0; t < nt; t++) {
        const int buf = t & 1;

        if (t + 1 < nt) {
            const int k0 = (t + 1) * 16;
            ra0 = *(const float4*)&A[(size_t)(rowBase + ar0) * K + k0 + ac];
            ra1 = *(const float4*)&A[(size_t)(rowBase + ar1) * K + k0 + ac];
            rb0 = bok ? *(const float4*)&B[(size_t)(k0 + bk0) * N + gn] : make_float4(0,0,0,0);
            rb1 = bok ? *(const float4*)&B[(size_t)(k0 + bk1) * N + gn] : make_float4(0,0,0,0);
        }

#pragma unroll
        for (int ks = 0; ks < 16; ks += 8) {
            float a[4][4], b[4][2];
#pragma unroll
            for (int i = 0; i < 4; i++) {
                const float* p0 = &As[buf][wr + i * 16 + qid][ks + rid];
                const float* p1 = &As[buf][wr + i * 16 + qid + 8][ks + rid];
                a[i][0] = p0[0];
                a[i][1] = p1[0];
                a[i][2] = p0[4];
                a[i][3] = p1[4];
            }
#pragma unroll
            for (int j = 0; j < 4; j++) {
                b[j][0] = Bs[buf][ks + rid][wc + j * 8 + qid];
                b[j][1] = Bs[buf][ks + rid + 4][wc + j * 8 + qid];
            }
#pragma unroll
            for (int i = 0; i < 4; i++)
#pragma unroll
                for (int j = 0; j < 4; j++)
                    mma_tf32(acc[i][j][0], acc[i][j][1], acc[i][j][2], acc[i][j][3],
                             a[i][0], a[i][1], a[i][2], a[i][3],
                             b[j][0], b[j][1]);
        }

        if (t + 1 < nt) {
            const int nb = (t + 1) & 1;
            *(float4*)&As[nb][ar0][ac] = to_tf32x4(ra0);
            *(float4*)&As[nb][ar1][ac] = to_tf32x4(ra1);
            *(float4*)&Bs[nb][bk0][bn] = to_tf32x4(rb0);
            *(float4*)&Bs[nb][bk1][bn] = to_tf32x4(rb1);
        }
        __syncthreads();
    }

#pragma unroll
    for (int i = 0; i < 4; i++) {
        const int r0 = rowBase + wr + i * 16 + qid;
#pragma unroll
        for (int j = 0; j < 4; j++) {
            const int col = colBase + wc + j * 8 + rid * 2;
            if (col < N) {
                if (Ch) {
                    __half2 h0 = __floats2half2_rn(acc[i][j][0], acc[i][j][1]);
                    __half2 h1 = __floats2half2_rn(acc[i][j][2], acc[i][j][3]);
                    *(__half2*)&Ch[(size_t)r0 * N + col]       = h0;
                    *(__half2*)&Ch[(size_t)(r0 + 8) * N + col] = h1;
                } else {
                    float2 v0 = make_float2(acc[i][j][0], acc[i][j][1]);
                    float2 v1 = make_float2(acc[i][j][2], acc[i][j][3]);
                    if (round_out) {
                        v0.x = to_tf32(v0.x); v0.y = to_tf32(v0.y);
                        v1.x = to_tf32(v1.x); v1.y = to_tf32(v1.y);
                    }
                    *(float2*)&C[(size_t)r0 * N + col]       = v0;
                    *(float2*)&C[(size_t)(r0 + 8) * N + col] = v1;
                }
            }
        }
    }
}

// ---------------------------------------------------------------------------
// RMSNorm (in place)
// ---------------------------------------------------------------------------
__global__ void rmsnorm_kernel(float* __restrict__ x,
                               const float* __restrict__ scale, int D)
{
    __shared__ float red[32];
    float* p = x + (size_t)blockIdx.x * D;

    float ss = 0.f;
    for (int d = threadIdx.x; d < D; d += blockDim.x) {
        float v = p[d];
        ss += v * v;
    }
#pragma unroll
    for (int o = 16; o; o >>= 1) ss += __shfl_xor_sync(0xffffffffu, ss, o);
    if ((threadIdx.x & 31) == 0) red[threadIdx.x >> 5] = ss;
    __syncthreads();
    if (threadIdx.x < 32) {
        float v = (threadIdx.x < (blockDim.x >> 5)) ? red[threadIdx.x] : 0.f;
#pragma unroll
        for (int o = 16; o; o >>= 1) v += __shfl_xor_sync(0xffffffffu, v, o);
        if (threadIdx.x == 0) red[0] = v;
    }
    __syncthreads();
    float inv = rsqrtf(red[0] / (float)D + EPS);
    for (int d = threadIdx.x; d < D; d += blockDim.x)
        p[d] = p[d] * inv * scale[d];
}

// ---------------------------------------------------------------------------
// RoPE tables / application (rope kernels emit fp16 for the attention mma)
// ---------------------------------------------------------------------------
__global__ void rope_table_kernel(float* __restrict__ ctab, float* __restrict__ stab)
{
    int idx = blockIdx.x * blockDim.x + threadIdx.x;
    if (idx >= S * (ROPE / 2)) return;
    int i = idx % (ROPE / 2);
    int s = idx / (ROPE / 2);
    float freq = (float)pow(10000.0, -((double)(2 * i)) / (double)ROPE);
    float ang  = (float)s * freq;
    double a   = (double)ang;
    ctab[idx] = (float)cos(a);
    stab[idx] = (float)sin(a);
}

__global__ void rope_q_kernel(const float* __restrict__ qf, __half* __restrict__ qh,
                              const float* __restrict__ ctab,
                              const float* __restrict__ stab)
{
    int idx = blockIdx.x * blockDim.x + threadIdx.x;
    if (idx >= T * NH * (ROPE / 2)) return;
    int i   = idx & 31;
    int rem = idx >> 5;
    int h   = rem & (NH - 1);
    int tok = rem >> 4;
    int s   = tok & (S - 1);
    float c  = ctab[s * 32 + i];
    float sn = stab[s * 32 + i];
    size_t off = (size_t)tok * (NH * ROPE) + h * ROPE + 2 * i;
    float x1 = qf[off], x2 = qf[off + 1];
    *(__half2*)&qh[off] = __floats2half2_rn(x1 * c - x2 * sn, x1 * sn + x2 * c);
}

__global__ void rope_k_kernel(const float* __restrict__ kf, __half* __restrict__ kh,
                              const float* __restrict__ ctab,
                              const float* __restrict__ stab)
{
    int idx = blockIdx.x * blockDim.x + threadIdx.x;
    if (idx >= T * (ROPE / 2)) return;
    int i   = idx & 31;
    int tok = idx >> 5;
    int s   = tok & (S - 1);
    float c  = ctab[s * 32 + i];
    float sn = stab[s * 32 + i];
    size_t off = (size_t)tok * ROPE + 2 * i;
    float x1 = kf[off], x2 = kf[off + 1];
    *(__half2*)&kh[off] = __floats2half2_rn((x1 * c - x2 * sn) * 0.0625f,
                                            (x1 * sn + x2 * c) * 0.0625f);
}

// ---------------------------------------------------------------------------
// Flash attention: BQ=128, 512 threads. QK AND PV on fp16 m16n8k16.
// V staged as k-pair-packed half2; P written as packed half2 by softmax.
// In-register softmax; skewed pipeline; register K/V prefetch.
// ---------------------------------------------------------------------------
constexpr int BQ  = 128;
constexpr int BKT = 64;
constexpr int VSTRH = 136;   // uint32 stride: B-reads rid*8+qid conflict-free
constexpr int PSTRH = 36;    // uint32 stride: A-reads qid*4+rid conflict-free

struct AttnSmem {
    uint32_t Qf[8 * 12 * 4 * 32];     // fp16 QK A-frag   49.2KB
    uint32_t Kf[8 * 12 * 2 * 32];     // fp16 QK B-frag   24.6KB
    uint32_t Vh[32 * VSTRH];          // fp16 V k-pairs   17.4KB
    uint32_t Ph[BQ * PSTRH];          // fp16 P k-pairs   18.4KB
    float rowmax[2][BQ];
    float rowsum[2][BQ];
};

__global__ void __launch_bounds__(512)
attn_kernel(const __half* __restrict__ qn, const __half* __restrict__ qr,
            const __half* __restrict__ kn, const __half* __restrict__ kr,
            const __half* __restrict__ v,  float* __restrict__ out)
{
    extern __shared__ char smraw[];
    AttnSmem& sm = *reinterpret_cast<AttnSmem*>(smraw);

    const int qt = (gridDim.x - 1) - blockIdx.x;   // heavy blocks first
    const int h  = blockIdx.y;
    const int b  = blockIdx.z;
    const int tid = threadIdx.x;
    const int lane = tid & 31;
    const int warp = tid >> 5;
    const int qid  = lane >> 2;
    const int rid  = lane & 3;
    const int qb = b * S + qt * BQ;

    const int mtile = warp & 7;
    const int half  = warp >> 3;
    const int ntb   = half * 4;
    const int row0 = mtile * 16 + qid;
    const int nbv  = half * 64;

    // staging indices: K tile (fp16) and V tile (fp16, row-pair packed)
    const int krow = tid & 63;
    const int kg   = tid >> 6;           // 0..7
    const int vrp  = tid >> 4;           // row pair 0..31
    const int vcg  = (tid & 15) * 8;     // col group base (half2 units)

    // ---- stage Q tile [128 x 192] halves into fp16 A-frag layout ----
    for (int idx = tid; idx < BQ * 16; idx += 512) {
        int r = idx & 127, g = idx >> 7;
        uint4 u = *(const uint4*)&qn[(size_t)(qb + r) * (NH * NOPE) + h * NOPE + g * 8];
        st_afrag_h(sm.Qf, r, g * 8, u);
    }
    for (int idx = tid; idx < BQ * 8; idx += 512) {
        int r = idx & 127, g = idx >> 7;
        uint4 u = *(const uint4*)&qr[(size_t)(qb + r) * (NH * ROPE) + h * ROPE + g * 8];
        st_afrag_h(sm.Qf, r, 128 + g * 8, u);
    }

    float m0 = -1e30f, m1 = -1e30f, l0 = 0.f, l1 = 0.f;
    float acc[8][4];
#pragma unroll
    for (int j = 0; j < 8; j++)
#pragma unroll
        for (int c = 0; c < 4; c++) acc[j][c] = 0.f;

    const int nkt = 2 * qt + 2;

    // ---- prologue: load tile 0 regs, stage Kf(0), prefetch K(1) ----
    uint4 kb[3], vlo, vhi;
    {
        const int kbT = b * S;
        kb[0] = *(const uint4*)&kn[(size_t)(kbT + krow) * (NH * NOPE) + h * NOPE + kg * 8];
        kb[1] = *(const uint4*)&kn[(size_t)(kbT + krow) * (NH * NOPE) + h * NOPE + kg * 8 + 64];
        kb[2] = *(const uint4*)&kr[(size_t)(kbT + krow) * ROPE + kg * 8];
        vlo = *(const uint4*)&v[(size_t)(kbT + 2 * vrp)     * (NH * VD) + h * VD + vcg];
        vhi = *(const uint4*)&v[(size_t)(kbT + 2 * vrp + 1) * (NH * VD) + h * VD + vcg];
    }
    st_bfrag_h(sm.Kf, krow, kg * 8, kb[0]);
    st_bfrag_h(sm.Kf, krow, kg * 8 + 64, kb[1]);
    st_bfrag_h(sm.Kf, krow, 128 + kg * 8, kb[2]);
    __syncthreads();            // Qf + Kf(0) visible
    if (1 < nkt) {
        const int kbT = b * S + BKT;
        kb[0] = *(const uint4*)&kn[(size_t)(kbT + krow) * (NH * NOPE) + h * NOPE + kg * 8];
        kb[1] = *(const uint4*)&kn[(size_t)(kbT + krow) * (NH * NOPE) + h * NOPE + kg * 8 + 64];
        kb[2] = *(const uint4*)&kr[(size_t)(kbT + krow) * ROPE + kg * 8];
    }

    for (int kt = 0; kt < nkt; kt++) {
        // ---- stage V(kt): interleave row pairs into half2 k-pairs ----
        {
            uint32_t* dst = &sm.Vh[vrp * VSTRH + vcg];
            uint4 o0, o1;
            o0.x = prmt(vlo.x, vhi.x, 0x5410); o0.y = prmt(vlo.x, vhi.x, 0x7632);
            o0.z = prmt(vlo.y, vhi.y, 0x5410); o0.w = prmt(vlo.y, vhi.y, 0x7632);
            o1.x = prmt(vlo.z, vhi.z, 0x5410); o1.y = prmt(vlo.z, vhi.z, 0x7632);
            o1.z = prmt(vlo.w, vhi.w, 0x5410); o1.w = prmt(vlo.w, vhi.w, 0x7632);
            *(uint4*)&dst[0] = o0;
            *(uint4*)&dst[4] = o1;
        }

        // ---- QK(kt) via fp16 m16n8k16 -> scores in registers ----
        float c[4][4];
#pragma unroll
        for (int j = 0; j < 4; j++)
#pragma unroll
            for (int cc = 0; cc < 4; cc++) c[j][cc] = 0.f;

#pragma unroll
        for (int ks = 0; ks < 12; ks++) {
            const uint32_t* ap = &sm.Qf[(((mtile * 12 + ks) * 4) << 5) + lane];
            uint32_t a0 = ap[0], a1 = ap[32], a2 = ap[64], a3 = ap[96];
#pragma unroll
            for (int j = 0; j < 4; j++) {
                const uint32_t* bp = &sm.Kf[((((ntb + j) * 12 + ks) * 2) << 5) + lane];
                mma_f16(c[j][0], c[j][1], c[j][2], c[j][3],
                        a0, a1, a2, a3, bp[0], bp[32]);
            }
        }

        // scale + mask in registers
        {
            const bool diag = (kt >= 2 * qt);
#pragma unroll
            for (int j = 0; j < 4; j++) {
                int col = (ntb + j) * 8 + rid * 2;
                int ki0 = kt * BKT + col;
                c[j][0] *= SM_SCALE2; c[j][1] *= SM_SCALE2;
                c[j][2] *= SM_SCALE2; c[j][3] *= SM_SCALE2;
                if (diag) {
                    int qi0 = qt * BQ + row0;
                    int qi1 = qi0 + 8;
                    if (ki0     > qi0) c[j][0] = MASK2;
                    if (ki0 + 1 > qi0) c[j][1] = MASK2;
                    if (ki0     > qi1) c[j][2] = MASK2;
                    if (ki0 + 1 > qi1) c[j][3] = MASK2;
                }
            }
        }

        // per-row max over this warp's 32 columns
        {
            float mx0 = fmaxf(fmaxf(c[0][0], c[0][1]), fmaxf(c[1][0], c[1][1]));
            mx0 = fmaxf(mx0, fmaxf(fmaxf(c[2][0], c[2][1]), fmaxf(c[3][0], c[3][1])));
            float mx1 = fmaxf(fmaxf(c[0][2], c[0][3]), fmaxf(c[1][2], c[1][3]));
            mx1 = fmaxf(mx1, fmaxf(fmaxf(c[2][2], c[2][3]), fmaxf(c[3][2], c[3][3])));
            mx0 = fmaxf(mx0, __shfl_xor_sync(0xffffffffu, mx0, 1));
            mx0 = fmaxf(mx0, __shfl_xor_sync(0xffffffffu, mx0, 2));
            mx1 = fmaxf(mx1, __shfl_xor_sync(0xffffffffu, mx1, 1));
            mx1 = fmaxf(mx1, __shfl_xor_sync(0xffffffffu, mx1, 2));
            if (rid == 0) {
                sm.rowmax[half][row0]     = mx0;
                sm.rowmax[half][row0 + 8] = mx1;
            }
        }
        __syncthreads();   // barA: rowmax halves + V(kt) stores visible

        // ---- combine max, exp from regs, write packed half2 P, sums ----
        float al0, al1;
        {
            float f0 = fmaxf(sm.rowmax[0][row0],     sm.rowmax[1][row0]);
            float f1 = fmaxf(sm.rowmax[0][row0 + 8], sm.rowmax[1][row0 + 8]);
            float mn0 = fmaxf(m0, f0);
            float mn1 = fmaxf(m1, f1);
            al0 = exp2f(m0 - mn0);
            al1 = exp2f(m1 - mn1);
            m0 = mn0; m1 = mn1;

            float ps0 = 0.f, ps1 = 0.f;
#pragma unroll
            for (int j = 0; j < 4; j++) {
                float e0 = exp2f(c[j][0] - mn0);
                float e1 = exp2f(c[j][1] - mn0);
                float e2 = exp2f(c[j][2] - mn1);
                float e3 = exp2f(c[j][3] - mn1);
                ps0 += e0 + e1;
                ps1 += e2 + e3;
                int pidx = (ntb + j) * 4 + rid;     // half2 index within row
                sm.Ph[row0 * PSTRH + pidx]       = h2_as_u32(__floats2half2_rn(e0, e1));
                sm.Ph[(row0 + 8) * PSTRH + pidx] = h2_as_u32(__floats2half2_rn(e2, e3));
            }
            ps0 += __shfl_xor_sync(0xffffffffu, ps0, 1);
            ps0 += __shfl_xor_sync(0xffffffffu, ps0, 2);
            ps1 += __shfl_xor_sync(0xffffffffu, ps1, 1);
            ps1 += __shfl_xor_sync(0xffffffffu, ps1, 2);
            if (rid == 0) {
                sm.rowsum[half][row0]     = ps0;
                sm.rowsum[half][row0 + 8] = ps1;
            }
        }

        // ---- stage Kf(kt+1); prefetch V(kt+1), K(kt+2) regs ----
        if (kt + 1 < nkt) {
            const int vT = b * S + (kt + 1) * BKT;
            vlo = *(const uint4*)&v[(size_t)(vT + 2 * vrp)     * (NH * VD) + h * VD + vcg];
            vhi = *(const uint4*)&v[(size_t)(vT + 2 * vrp + 1) * (NH * VD) + h * VD + vcg];
            st_bfrag_h(sm.Kf, krow, kg * 8, kb[0]);
            st_bfrag_h(sm.Kf, krow, kg * 8 + 64, kb[1]);
            st_bfrag_h(sm.Kf, krow, 128 + kg * 8, kb[2]);
            if (kt + 2 < nkt) {
                const int kT = b * S + (kt + 2) * BKT;
                kb[0] = *(const uint4*)&kn[(size_t)(kT + krow) * (NH * NOPE) + h * NOPE + kg * 8];
                kb[1] = *(const uint4*)&kn[(size_t)(kT + krow) * (NH * NOPE) + h * NOPE + kg * 8 + 64];
                kb[2] = *(const uint4*)&kr[(size_t)(kT + krow) * ROPE + kg * 8];
            }
        }
        __syncthreads();   // barB: Ph + rowsum + Kf(kt+1) visible

        // ---- l update + PV(kt) via fp16 m16n8k16 ----
        {
            l0 = l0 * al0 + (sm.rowsum[0][row0]     + sm.rowsum[1][row0]);
            l1 = l1 * al1 + (sm.rowsum[0][row0 + 8] + sm.rowsum[1][row0 + 8]);
#pragma unroll
            for (int j = 0; j < 8; j++) {
                acc[j][0] *= al0; acc[j][1] *= al0;
                acc[j][2] *= al1; acc[j][3] *= al1;
            }
#pragma unroll
            for (int ks = 0; ks < 4; ks++) {
                const uint32_t a0 = sm.Ph[row0 * PSTRH + ks * 8 + rid];
                const uint32_t a1 = sm.Ph[(row0 + 8) * PSTRH + ks * 8 + rid];
                const uint32_t a2 = sm.Ph[row0 * PSTRH + ks * 8 + rid + 4];
                const uint32_t a3 = sm.Ph[(row0 + 8) * PSTRH + ks * 8 + rid + 4];
#pragma unroll
                for (int j = 0; j < 8; j++) {
                    const uint32_t b0 = sm.Vh[(ks * 8 + rid)     * VSTRH + nbv + j * 8 + qid];
                    const uint32_t b1 = sm.Vh[(ks * 8 + rid + 4) * VSTRH + nbv + j * 8 + qid];
                    mma_f16(acc[j][0], acc[j][1], acc[j][2], acc[j][3],
                            a0, a1, a2, a3, b0, b1);
                }
            }
        }
        __syncthreads();   // barC: PV(kt) drained; Vh/Ph/rowmax free
    }

    // ---- epilogue: scale by 1/l, write out ----
    {
        const float il0 = 1.f / l0;
        const float il1 = 1.f / l1;
        const int tok0 = qb + row0;
        const int tok1 = tok0 + 8;
#pragma unroll
        for (int j = 0; j < 8; j++) {
            const int col = nbv + j * 8 + rid * 2;
            *(float2*)&out[(size_t)tok0 * (NH * VD) + h * VD + col] =
                make_float2(acc[j][0] * il0, acc[j][1] * il0);
            *(float2*)&out[(size_t)tok1 * (NH * VD) + h * VD + col] =
                make_float2(acc[j][2] * il1, acc[j][3] * il1);
        }
    }
}

// ---------------------------------------------------------------------------
// Launch (Q path and KV path forked onto concurrent streams inside capture)
// ---------------------------------------------------------------------------
static void launch_gemm_s(cudaStream_t s, const float* A, const float* B, float* C,
                          int M, int N, int K, int round_out = 0, __half* Ch = nullptr)
{
    dim3 grid((N + 127) / 128, (M + 127) / 128);
    tf32_gemm_kernel<<<grid, 256, 0, s>>>(A, B, C, Ch, M, N, K, round_out);
}

extern "C" void kernel_launch(void* const* d_in, const int* in_sizes, int n_in,
                              void* d_out, int out_size)
{
    const float* x         = (const float*)d_in[0];
    const float* W_cq      = (const float*)d_in[1];
    const float* q_scale   = (const float*)d_in[2];
    const float* W_dq_nope = (const float*)d_in[3];
    const float* W_dq_rope = (const float*)d_in[4];
    const float* W_ckv     = (const float*)d_in[5];
    const float* kv_scale  = (const float*)d_in[6];
    const float* W_dk_nope = (const float*)d_in[7];
    const float* W_dv      = (const float*)d_in[8];
    const float* W_krope   = (const float*)d_in[9];
    const float* W_o       = (const float*)d_in[10];
    float* out = (float*)d_out;

    float *cq, *ckv, *qrf, *krf, *att, *ctab, *stab;
    __half *qnh, *knh, *qrh, *krh, *vvh;
    cudaGetSymbolAddress((void**)&cq,   g_cq);
    cudaGetSymbolAddress((void**)&ckv,  g_ckv);
    cudaGetSymbolAddress((void**)&qrf,  g_qrope_f);
    cudaGetSymbolAddress((void**)&krf,  g_krope_f);
    cudaGetSymbolAddress((void**)&att,  g_attn);
    cudaGetSymbolAddress((void**)&ctab, g_ctab);
    cudaGetSymbolAddress((void**)&stab, g_stab);
    cudaGetSymbolAddress((void**)&qnh,  g_qnope_h);
    cudaGetSymbolAddress((void**)&knh,  g_knope_h);
    cudaGetSymbolAddress((void**)&qrh,  g_qrope_h);
    cudaGetSymbolAddress((void**)&krh,  g_krope_h);
    cudaGetSymbolAddress((void**)&vvh,  g_v_h);

    // Fork/join machinery (host-only cost; harness times graph replays).
    cudaStream_t s0 = 0;
    cudaStream_t skv;
    cudaEvent_t ev_fork, ev_kv;
    cudaStreamCreateWithFlags(&skv, cudaStreamNonBlocking);
    cudaEventCreateWithFlags(&ev_fork, cudaEventDisableTiming);
    cudaEventCreateWithFlags(&ev_kv,  cudaEventDisableTiming);

    // RoPE tables (needed by both paths)
    rope_table_kernel<<<(S * 32 + 255) / 256, 256, 0, s0>>>(ctab, stab);

    // ---- fork: KV path on skv ----
    cudaEventRecord(ev_fork, s0);
    cudaStreamWaitEvent(skv, ev_fork, 0);

    // KV path (skv)
    launch_gemm_s(skv, x, W_krope, krf, T, ROPE, H);
    rope_k_kernel<<<(T * 32 + 255) / 256, 256, 0, skv>>>(krf, krh, ctab, stab);
    launch_gemm_s(skv, x, W_ckv, ckv, T, KVR, H);
    rmsnorm_kernel<<<T, 256, 0, skv>>>(ckv, kv_scale, KVR);
    launch_gemm_s(skv, ckv, W_dk_nope, nullptr, T, NH * NOPE, KVR, 0, knh); // fp16 out
    launch_gemm_s(skv, ckv, W_dv, nullptr, T, NH * VD, KVR, 0, vvh);        // fp16 out
    cudaEventRecord(ev_kv, skv);

    // Q path (s0)
    launch_gemm_s(s0, x, W_cq, cq, T, QR, H);
    rmsnorm_kernel<<<T, 256, 0, s0>>>(cq, q_scale, QR);
    launch_gemm_s(s0, cq, W_dq_nope, nullptr, T, NH * NOPE, QR, 0, qnh);    // fp16 out
    launch_gemm_s(s0, cq, W_dq_rope, qrf, T, NH * ROPE, QR);
    rope_q_kernel<<<(T * NH * 32 + 255) / 256, 256, 0, s0>>>(qrf, qrh, ctab, stab);

    // ---- join ----
    cudaStreamWaitEvent(s0, ev_kv, 0);

    // Attention
    cudaFuncSetAttribute((const void*)attn_kernel,
                         cudaFuncAttributeMaxDynamicSharedMemorySize,
                         (int)sizeof(AttnSmem));
    attn_kernel<<<dim3(S / BQ, NH, BB), 512, sizeof(AttnSmem), s0>>>(qnh, qrh, knh, krh, vvh, att);

    // Output projection
    launch_gemm_s(s0, att, W_o, out, T, H, NH * VD);
}